// round 9
// baseline (speedup 1.0000x reference)
#include <cuda_runtime.h>
#include <math.h>
#include <stdint.h>

#define Bn 32768
#define Dn 256
#define KN 32
#define FFn 1024

// residual after attention
__device__ float g_x[Bn * Dn];
// frag-ordered pre-split tf32 weights: uint4 {hi(b0), lo(b0), hi(b1), lo(b1)}
__device__ uint4 g_wqf[32 * 32 * 32];
__device__ uint4 g_wof[32 * 32 * 32];
__device__ uint4 g_wkf[8 * 4 * 32 * 32];
__device__ uint4 g_wvf[8 * 32 * 4 * 32];
__device__ uint4 g_w1f[32 * 128 * 32];
__device__ uint4 g_w2f[128 * 32 * 32];

// ---- attn smem layout (floats) ----
#define A_H  0          // hS  [16][268]
#define A_Q  4288       // qS  [16][268]   (alias oS)
#define A_C  8576       // cS  [128][268]  (alias uS, u rows = h*16+a)
#define A_S  42880      // sS  [128][33]   rows = a*8+h
#define A_A4 47104      // aS4 [16][264]   attn as [a][k][h]
#define ATTN_SMEM (51328 * 4)

// ---- ffn smem (uint2 words) ----
#define FH_STRIDE 266   // hHL [64][266]
#define FA_STRIDE 131   // act [64][131]  (128-col chunk)
#define FFN_SMEM ((64 * FH_STRIDE + 64 * FA_STRIDE) * 8)

__device__ __forceinline__ uint32_t f2tf(float f) {
    uint32_t u;
    asm("cvt.rna.tf32.f32 %0, %1;" : "=r"(u) : "f"(f));
    return u;
}

__device__ __forceinline__ void mma8(float* c, const uint32_t* a, const uint32_t* b) {
    asm volatile(
        "mma.sync.aligned.m16n8k8.row.col.f32.tf32.tf32.f32 "
        "{%0,%1,%2,%3}, {%4,%5,%6,%7}, {%8,%9}, {%0,%1,%2,%3};"
        : "+f"(c[0]), "+f"(c[1]), "+f"(c[2]), "+f"(c[3])
        : "r"(a[0]), "r"(a[1]), "r"(a[2]), "r"(a[3]), "r"(b[0]), "r"(b[1]));
}

__device__ __forceinline__ uint4 splitpair(float b0, float b1) {
    uint4 r;
    r.x = f2tf(b0); r.y = f2tf(b0 - __uint_as_float(r.x));
    r.z = f2tf(b1); r.w = f2tf(b1 - __uint_as_float(r.z));
    return r;
}

// ---------------------------------------------------------------------------
__global__ void split_all(
    const float* __restrict__ Wq, const float* __restrict__ Wk,
    const float* __restrict__ Wv, const float* __restrict__ Wo,
    const float* __restrict__ ff1w, const float* __restrict__ ff2w)
{
    int gid = blockIdx.x * 256 + threadIdx.x;
    if (gid < 32768) {                                    // Wq
        int lane = gid & 31, t = gid >> 5;
        int ntile = t & 31, ks = t >> 5;
        int lg = lane >> 2, lc = lane & 3;
        int k0 = ks * 8 + lc, n = ntile * 8 + lg;
        g_wqf[gid] = splitpair(Wq[k0 * 256 + n], Wq[(k0 + 4) * 256 + n]);
    } else if (gid < 65536) {                             // Wo
        int e = gid - 32768;
        int lane = e & 31, t = e >> 5;
        int ntile = t & 31, ks = t >> 5;
        int lg = lane >> 2, lc = lane & 3;
        int k0 = ks * 8 + lc, n = ntile * 8 + lg;
        g_wof[e] = splitpair(Wo[k0 * 256 + n], Wo[(k0 + 4) * 256 + n]);
    } else if (gid < 98304) {                             // Wk per head (transposed)
        int e = gid - 65536;
        int lane = e & 31, t = e >> 5;
        int ntile = t & 31, hk = t >> 5;
        int h = hk >> 2, ks = hk & 3;
        int lg = lane >> 2, lc = lane & 3;
        int k0 = ks * 8 + lc, n = ntile * 8 + lg;
        g_wkf[e] = splitpair(Wk[n * 256 + h * 32 + k0],
                             Wk[n * 256 + h * 32 + k0 + 4]);
    } else if (gid < 229376) {                            // ff1w
        int e = gid - 98304;
        int lane = e & 31, t = e >> 5;
        int ntile = t & 127, ks = t >> 7;
        int lg = lane >> 2, lc = lane & 3;
        int k0 = ks * 8 + lc, n = ntile * 8 + lg;
        g_w1f[e] = splitpair(ff1w[k0 * FFn + n], ff1w[(k0 + 4) * FFn + n]);
    } else if (gid < 360448) {                            // ff2w
        int e = gid - 229376;
        int lane = e & 31, t = e >> 5;
        int ntile = t & 31, ks = t >> 5;
        int lg = lane >> 2, lc = lane & 3;
        int k0 = ks * 8 + lc, n = ntile * 8 + lg;
        g_w2f[e] = splitpair(ff2w[k0 * 256 + n], ff2w[(k0 + 4) * 256 + n]);
    } else if (gid < 393216) {                            // Wv per head
        int e = gid - 360448;
        int lane = e & 31, t = e >> 5;        // t in [0,1024)
        int nt = t & 3;
        int u2 = t >> 2;                      // [0,256)
        int ks = u2 & 31, hd = u2 >> 5;
        int lg = lane >> 2, lc = lane & 3;
        int k0 = ks * 8 + lc, n = hd * 32 + nt * 8 + lg;
        g_wvf[e] = splitpair(Wv[k0 * 256 + n], Wv[(k0 + 4) * 256 + n]);
    }
}

// ---------------------------------------------------------------------------
// Attention: 16 anchors / CTA, 512 threads, 1 CTA/SM.
// LN1 -> Q(mma,M16) -> c(mma per head,M16) -> scores -> softmax ->
// u(scalar, float4 attn) -> Wv(mma per head,M16) -> Wo(mma,M16)+residual.
// ---------------------------------------------------------------------------
__global__ __launch_bounds__(512, 1) void attn8(
    const float* __restrict__ x_anc, const float* __restrict__ x_nei,
    const float* __restrict__ g1, const float* __restrict__ b1)
{
    extern __shared__ float sf[];
    float* hS  = sf + A_H;
    float* qS  = sf + A_Q;       // alias oS
    float* cS  = sf + A_C;       // alias uS
    float* sS  = sf + A_S;
    float* aS4 = sf + A_A4;
    float* uS  = cS;
    float* oS  = qS;

    const int tid = threadIdx.x, wid = tid >> 5, lane = tid & 31;
    const int lg = lane >> 2, lc = lane & 3;
    const int j2 = tid & 255;
    const int b0 = blockIdx.x * 16;

    // ---- LN1: warp w -> row w ----
    {
        const float* xr = x_anc + (size_t)(b0 + wid) * Dn;
        float4 v0 = *(const float4*)&xr[lane * 8];
        float4 v1 = *(const float4*)&xr[lane * 8 + 4];
        float v[8] = {v0.x, v0.y, v0.z, v0.w, v1.x, v1.y, v1.z, v1.w};
        float s = 0.f, s2 = 0.f;
        #pragma unroll
        for (int t = 0; t < 8; t++) { s += v[t]; s2 += v[t] * v[t]; }
        #pragma unroll
        for (int o = 16; o; o >>= 1) {
            s  += __shfl_xor_sync(0xffffffffu, s,  o);
            s2 += __shfl_xor_sync(0xffffffffu, s2, o);
        }
        const float mu   = s * (1.0f / Dn);
        const float var  = s2 * (1.0f / Dn) - mu * mu;
        const float rstd = rsqrtf(var + 1e-5f);
        #pragma unroll
        for (int t = 0; t < 8; t++) {
            const int c = lane * 8 + t;
            hS[wid * 268 + c] = (v[t] - mu) * rstd * g1[c] + b1[c];
        }
    }
    __syncthreads();

    // ---- Q = h @ Wq via mma, M=16 (full tile) ----
    {
        float acc[2][4] = {{0.f,0.f,0.f,0.f},{0.f,0.f,0.f,0.f}};
        for (int ks = 0; ks < 32; ks++) {
            const int kb = ks * 8;
            float f0 = hS[lg * 268 + kb + lc];
            float f1 = hS[(lg + 8) * 268 + kb + lc];
            float f2 = hS[lg * 268 + kb + lc + 4];
            float f3 = hS[(lg + 8) * 268 + kb + lc + 4];
            uint32_t ahi[4], alo[4];
            ahi[0] = f2tf(f0); alo[0] = f2tf(f0 - __uint_as_float(ahi[0]));
            ahi[1] = f2tf(f1); alo[1] = f2tf(f1 - __uint_as_float(ahi[1]));
            ahi[2] = f2tf(f2); alo[2] = f2tf(f2 - __uint_as_float(ahi[2]));
            ahi[3] = f2tf(f3); alo[3] = f2tf(f3 - __uint_as_float(ahi[3]));
            #pragma unroll
            for (int nt = 0; nt < 2; nt++) {
                uint4 v = g_wqf[(ks * 32 + wid * 2 + nt) * 32 + lane];
                uint32_t bhi[2] = {v.x, v.z}, blo[2] = {v.y, v.w};
                mma8(acc[nt], alo, bhi);
                mma8(acc[nt], ahi, blo);
                mma8(acc[nt], ahi, bhi);
            }
        }
        #pragma unroll
        for (int nt = 0; nt < 2; nt++) {
            const int col = wid * 16 + nt * 8 + lc * 2;
            qS[lg * 268 + col]           = acc[nt][0];
            qS[lg * 268 + col + 1]       = acc[nt][1];
            qS[(lg + 8) * 268 + col]     = acc[nt][2];
            qS[(lg + 8) * 268 + col + 1] = acc[nt][3];
        }
    }
    __syncthreads();

    // ---- c[a][h][:] via mma per head, M=16 ----
    {
        #pragma unroll
        for (int h = 0; h < 8; h++) {
            float acc[2][4] = {{0.f,0.f,0.f,0.f},{0.f,0.f,0.f,0.f}};
            #pragma unroll
            for (int ks = 0; ks < 4; ks++) {
                const int kb = h * 32 + ks * 8;
                float f0 = qS[lg * 268 + kb + lc];
                float f1 = qS[(lg + 8) * 268 + kb + lc];
                float f2 = qS[lg * 268 + kb + lc + 4];
                float f3 = qS[(lg + 8) * 268 + kb + lc + 4];
                uint32_t ahi[4], alo[4];
                ahi[0] = f2tf(f0); alo[0] = f2tf(f0 - __uint_as_float(ahi[0]));
                ahi[1] = f2tf(f1); alo[1] = f2tf(f1 - __uint_as_float(ahi[1]));
                ahi[2] = f2tf(f2); alo[2] = f2tf(f2 - __uint_as_float(ahi[2]));
                ahi[3] = f2tf(f3); alo[3] = f2tf(f3 - __uint_as_float(ahi[3]));
                #pragma unroll
                for (int nt = 0; nt < 2; nt++) {
                    uint4 v = g_wkf[((h * 4 + ks) * 32 + wid * 2 + nt) * 32 + lane];
                    uint32_t bhi[2] = {v.x, v.z}, blo[2] = {v.y, v.w};
                    mma8(acc[nt], alo, bhi);
                    mma8(acc[nt], ahi, blo);
                    mma8(acc[nt], ahi, bhi);
                }
            }
            #pragma unroll
            for (int nt = 0; nt < 2; nt++) {
                const int col = wid * 16 + nt * 8 + lc * 2;
                cS[(lg * 8 + h) * 268 + col]           = acc[nt][0];
                cS[(lg * 8 + h) * 268 + col + 1]       = acc[nt][1];
                cS[((lg + 8) * 8 + h) * 268 + col]     = acc[nt][2];
                cS[((lg + 8) * 8 + h) * 268 + col + 1] = acc[nt][3];
            }
        }
    }
    __syncthreads();

    // ---- scores: warp = anchor (aa=wid), lane = neighbor ----
    {
        const int aa = wid;
        const float* xb = x_nei + (size_t)(b0 + aa) * (KN * Dn) + lane * Dn;
        float pr[8];
        #pragma unroll
        for (int h = 0; h < 8; h++) pr[h] = 0.f;
        #pragma unroll 8
        for (int i = 0; i < 64; i++) {
            float4 x4 = *(const float4*)&xb[i * 4];
            #pragma unroll
            for (int h = 0; h < 8; h++) {
                float4 c4 = *(const float4*)&cS[(aa * 8 + h) * 268 + i * 4];
                pr[h] = fmaf(x4.x, c4.x, fmaf(x4.y, c4.y,
                        fmaf(x4.z, c4.z, fmaf(x4.w, c4.w, pr[h]))));
            }
        }
        #pragma unroll
        for (int h = 0; h < 8; h++)
            sS[(aa * 8 + h) * 33 + lane] = pr[h];
    }
    __syncthreads();

    // ---- softmax: warp handles 8 (a,h) rows; write aS4[a][k][h] ----
    {
        #pragma unroll
        for (int rr = 0; rr < 8; rr++) {
            const int r = wid * 8 + rr;
            const int a = r >> 3, h = r & 7;
            float sc = sS[r * 33 + lane] * 0.17677669529663687f;
            float m = sc;
            #pragma unroll
            for (int o = 16; o; o >>= 1)
                m = fmaxf(m, __shfl_xor_sync(0xffffffffu, m, o));
            float e = expf(sc - m), es = e;
            #pragma unroll
            for (int o = 16; o; o >>= 1)
                es += __shfl_xor_sync(0xffffffffu, es, o);
            aS4[a * 264 + lane * 8 + h] = e / es;
        }
    }
    __syncthreads();

    // ---- u: thread j2 covers col j2 for 8 anchors (half-split) ----
    {
        const int a0g = (tid >> 8) * 8;
        for (int a = 0; a < 8; a++) {
            const int ag = a0g + a;
            const float* xb = x_nei + (size_t)(b0 + ag) * (KN * Dn) + j2;
            float u[8] = {0.f,0.f,0.f,0.f,0.f,0.f,0.f,0.f};
            #pragma unroll
            for (int k = 0; k < 32; k++) {
                float xv = xb[k * Dn];
                float4 af0 = *(const float4*)&aS4[ag * 264 + k * 8];
                float4 af1 = *(const float4*)&aS4[ag * 264 + k * 8 + 4];
                u[0] = fmaf(af0.x, xv, u[0]);
                u[1] = fmaf(af0.y, xv, u[1]);
                u[2] = fmaf(af0.z, xv, u[2]);
                u[3] = fmaf(af0.w, xv, u[3]);
                u[4] = fmaf(af1.x, xv, u[4]);
                u[5] = fmaf(af1.y, xv, u[5]);
                u[6] = fmaf(af1.z, xv, u[6]);
                u[7] = fmaf(af1.w, xv, u[7]);
            }
            #pragma unroll
            for (int h = 0; h < 8; h++)
                uS[(h * 16 + ag) * 268 + j2] = u[h];
        }
    }
    __syncthreads();

    // ---- Wv via mma per head: out[a][hd*32+n'] = u[(hd,a)][:] @ Wv-slice ----
    {
        #pragma unroll
        for (int uu = 0; uu < 2; uu++) {
            const int unit = wid * 2 + uu;         // [0,32)
            const int hd = unit >> 2, nt = unit & 3;
            float acc[4] = {0.f, 0.f, 0.f, 0.f};
            for (int ks = 0; ks < 32; ks++) {
                const int kb = ks * 8;
                float f0 = uS[(hd * 16 + lg) * 268 + kb + lc];
                float f1 = uS[(hd * 16 + lg + 8) * 268 + kb + lc];
                float f2 = uS[(hd * 16 + lg) * 268 + kb + lc + 4];
                float f3 = uS[(hd * 16 + lg + 8) * 268 + kb + lc + 4];
                uint32_t ahi[4], alo[4];
                ahi[0] = f2tf(f0); alo[0] = f2tf(f0 - __uint_as_float(ahi[0]));
                ahi[1] = f2tf(f1); alo[1] = f2tf(f1 - __uint_as_float(ahi[1]));
                ahi[2] = f2tf(f2); alo[2] = f2tf(f2 - __uint_as_float(ahi[2]));
                ahi[3] = f2tf(f3); alo[3] = f2tf(f3 - __uint_as_float(ahi[3]));
                uint4 v = g_wvf[((hd * 32 + ks) * 4 + nt) * 32 + lane];
                uint32_t bhi[2] = {v.x, v.z}, blo[2] = {v.y, v.w};
                mma8(acc, alo, bhi);
                mma8(acc, ahi, blo);
                mma8(acc, ahi, bhi);
            }
            const int col = hd * 32 + nt * 8 + lc * 2;
            oS[lg * 268 + col]           = acc[0];
            oS[lg * 268 + col + 1]       = acc[1];
            oS[(lg + 8) * 268 + col]     = acc[2];
            oS[(lg + 8) * 268 + col + 1] = acc[3];
        }
    }
    __syncthreads();

    // ---- x = x_anc + oS @ Wo via mma, M=16 ----
    {
        float acc[2][4] = {{0.f,0.f,0.f,0.f},{0.f,0.f,0.f,0.f}};
        for (int ks = 0; ks < 32; ks++) {
            const int kb = ks * 8;
            float f0 = oS[lg * 268 + kb + lc];
            float f1 = oS[(lg + 8) * 268 + kb + lc];
            float f2 = oS[lg * 268 + kb + lc + 4];
            float f3 = oS[(lg + 8) * 268 + kb + lc + 4];
            uint32_t ahi[4], alo[4];
            ahi[0] = f2tf(f0); alo[0] = f2tf(f0 - __uint_as_float(ahi[0]));
            ahi[1] = f2tf(f1); alo[1] = f2tf(f1 - __uint_as_float(ahi[1]));
            ahi[2] = f2tf(f2); alo[2] = f2tf(f2 - __uint_as_float(ahi[2]));
            ahi[3] = f2tf(f3); alo[3] = f2tf(f3 - __uint_as_float(ahi[3]));
            #pragma unroll
            for (int nt = 0; nt < 2; nt++) {
                uint4 v = g_wof[(ks * 32 + wid * 2 + nt) * 32 + lane];
                uint32_t bhi[2] = {v.x, v.z}, blo[2] = {v.y, v.w};
                mma8(acc[nt], alo, bhi);
                mma8(acc[nt], ahi, blo);
                mma8(acc[nt], ahi, bhi);
            }
        }
        #pragma unroll
        for (int nt = 0; nt < 2; nt++) {
            const int col = wid * 16 + nt * 8 + lc * 2;
            const size_t i0 = (size_t)(b0 + lg) * Dn + col;
            const size_t i1 = (size_t)(b0 + lg + 8) * Dn + col;
            g_x[i0]     = x_anc[i0]     + acc[nt][0];
            g_x[i0 + 1] = x_anc[i0 + 1] + acc[nt][1];
            g_x[i1]     = x_anc[i1]     + acc[nt][2];
            g_x[i1 + 1] = x_anc[i1 + 1] + acc[nt][3];
        }
    }
}

// ---------------------------------------------------------------------------
// FFN: 64 rows / CTA (512 CTAs), 512 threads. Warps = 4 M-groups x 4 N-groups.
// FF processed in 8 chunks of 128 cols; act pre-split uint2.
// ---------------------------------------------------------------------------
__global__ __launch_bounds__(512, 1) void ffn_mma4(
    const float* __restrict__ ln2g, const float* __restrict__ ln2b,
    const float* __restrict__ ff1b, const float* __restrict__ ff2b,
    float* __restrict__ out)
{
    extern __shared__ uint2 su[];
    uint2* hHL = su;                      // [64][266]
    uint2* act = su + 64 * FH_STRIDE;     // [64][131]

    const int tid = threadIdx.x, wid = tid >> 5, lane = tid & 31;
    const int lg = lane >> 2, lc = lane & 3;
    const int wm = wid >> 2, wn = wid & 3;
    const int row0 = blockIdx.x * 64;

    // ---- LN2: warp handles 4 rows ----
    #pragma unroll
    for (int rr = 0; rr < 4; rr++) {
        const int row = wid * 4 + rr;
        const float* xr = g_x + (size_t)(row0 + row) * Dn;
        float4 v0 = *(const float4*)&xr[lane * 8];
        float4 v1 = *(const float4*)&xr[lane * 8 + 4];
        float v[8] = {v0.x, v0.y, v0.z, v0.w, v1.x, v1.y, v1.z, v1.w};
        float s = 0.f, s2 = 0.f;
        #pragma unroll
        for (int t = 0; t < 8; t++) { s += v[t]; s2 += v[t] * v[t]; }
        #pragma unroll
        for (int o = 16; o; o >>= 1) {
            s  += __shfl_xor_sync(0xffffffffu, s,  o);
            s2 += __shfl_xor_sync(0xffffffffu, s2, o);
        }
        const float mu   = s * (1.0f / Dn);
        const float var  = s2 * (1.0f / Dn) - mu * mu;
        const float rstd = rsqrtf(var + 1e-5f);
        #pragma unroll
        for (int t = 0; t < 8; t++) {
            const int c = lane * 8 + t;
            float hv = (v[t] - mu) * rstd * ln2g[c] + ln2b[c];
            uint32_t hi = f2tf(hv);
            hHL[row * FH_STRIDE + c] = make_uint2(hi, f2tf(hv - __uint_as_float(hi)));
        }
    }
    __syncthreads();

    float acc2[8][4];
    #pragma unroll
    for (int nt = 0; nt < 8; nt++)
        #pragma unroll
        for (int e = 0; e < 4; e++) acc2[nt][e] = 0.f;

    for (int cc = 0; cc < 8; cc++) {
        // ---- ff1 chunk: rows wm*16, cols wn*32 + nt*8 within 128-col chunk ----
        float acc[4][4];
        #pragma unroll
        for (int nt = 0; nt < 4; nt++)
            #pragma unroll
            for (int e = 0; e < 4; e++) acc[nt][e] = 0.f;

        for (int ks = 0; ks < 32; ks++) {
            const int kb = ks * 8;
            const int r0 = wm * 16 + lg;
            uint2 p0 = hHL[r0 * FH_STRIDE + kb + lc];
            uint2 p1 = hHL[(r0 + 8) * FH_STRIDE + kb + lc];
            uint2 p2 = hHL[r0 * FH_STRIDE + kb + lc + 4];
            uint2 p3 = hHL[(r0 + 8) * FH_STRIDE + kb + lc + 4];
            uint32_t ahi[4] = {p0.x, p1.x, p2.x, p3.x};
            uint32_t alo[4] = {p0.y, p1.y, p2.y, p3.y};
            #pragma unroll
            for (int nt = 0; nt < 4; nt++) {
                const int ntile = cc * 16 + wn * 4 + nt;
                uint4 v = g_w1f[(ks * 128 + ntile) * 32 + lane];
                uint32_t bhi[2] = {v.x, v.z}, blo[2] = {v.y, v.w};
                mma8(acc[nt], alo, bhi);
                mma8(acc[nt], ahi, blo);
                mma8(acc[nt], ahi, bhi);
            }
        }

        // ---- bias + gelu -> pre-split act ----
        {
            const int r0 = wm * 16 + lg;
            #pragma unroll
            for (int nt = 0; nt < 4; nt++) {
                const int lcol = wn * 32 + nt * 8 + lc * 2;
                const int gcol = cc * 128 + lcol;
                #pragma unroll
                for (int e = 0; e < 2; e++) {
                    const float bb = ff1b[gcol + e];
                    float u0 = acc[nt][e] + bb;
                    float u1 = acc[nt][2 + e] + bb;
                    float g0 = 0.5f * u0 * (1.0f + erff(u0 * 0.70710678118654752f));
                    float g1v = 0.5f * u1 * (1.0f + erff(u1 * 0.70710678118654752f));
                    uint32_t h0 = f2tf(g0), h1 = f2tf(g1v);
                    act[r0 * FA_STRIDE + lcol + e] =
                        make_uint2(h0, f2tf(g0 - __uint_as_float(h0)));
                    act[(r0 + 8) * FA_STRIDE + lcol + e] =
                        make_uint2(h1, f2tf(g1v - __uint_as_float(h1)));
                }
            }
        }
        __syncthreads();

        // ---- ff2 partial over this chunk's 128 K-values ----
        for (int kk2 = 0; kk2 < 16; kk2++) {
            const int kb = kk2 * 8;
            const int r0 = wm * 16 + lg;
            uint2 p0 = act[r0 * FA_STRIDE + kb + lc];
            uint2 p1 = act[(r0 + 8) * FA_STRIDE + kb + lc];
            uint2 p2 = act[r0 * FA_STRIDE + kb + lc + 4];
            uint2 p3 = act[(r0 + 8) * FA_STRIDE + kb + lc + 4];
            uint32_t ahi[4] = {p0.x, p1.x, p2.x, p3.x};
            uint32_t alo[4] = {p0.y, p1.y, p2.y, p3.y};
            const int ksg = cc * 16 + kk2;
            #pragma unroll
            for (int nt = 0; nt < 8; nt++) {
                const int ntile = wn * 8 + nt;
                uint4 v = g_w2f[(ksg * 32 + ntile) * 32 + lane];
                uint32_t bhi[2] = {v.x, v.z}, blo[2] = {v.y, v.w};
                mma8(acc2[nt], alo, bhi);
                mma8(acc2[nt], ahi, blo);
                mma8(acc2[nt], ahi, bhi);
            }
        }
        __syncthreads();
    }

    // ---- epilogue: residual + ff2 bias ----
    {
        const int r0 = wm * 16 + lg;
        #pragma unroll
        for (int nt = 0; nt < 8; nt++) {
            const int col = wn * 64 + nt * 8 + lc * 2;
            const float b0 = ff2b[col], b1 = ff2b[col + 1];
            const size_t i0 = (size_t)(row0 + r0) * Dn + col;
            const size_t i1 = (size_t)(row0 + r0 + 8) * Dn + col;
            out[i0]     = g_x[i0]     + acc2[nt][0] + b0;
            out[i0 + 1] = g_x[i0 + 1] + acc2[nt][1] + b1;
            out[i1]     = g_x[i1]     + acc2[nt][2] + b0;
            out[i1 + 1] = g_x[i1 + 1] + acc2[nt][3] + b1;
        }
    }
}

extern "C" void kernel_launch(void* const* d_in, const int* in_sizes, int n_in,
                              void* d_out, int out_size)
{
    const float* x_anc = (const float*)d_in[0];
    const float* x_nei = (const float*)d_in[1];
    const float* Wq    = (const float*)d_in[2];
    const float* Wk    = (const float*)d_in[3];
    const float* Wv    = (const float*)d_in[4];
    const float* Wo    = (const float*)d_in[5];
    const float* ln1g  = (const float*)d_in[6];
    const float* ln1b  = (const float*)d_in[7];
    const float* ln2g  = (const float*)d_in[8];
    const float* ln2b  = (const float*)d_in[9];
    const float* ff1w  = (const float*)d_in[10];
    const float* ff1b  = (const float*)d_in[11];
    const float* ff2w  = (const float*)d_in[12];
    const float* ff2b  = (const float*)d_in[13];
    float* out = (float*)d_out;

    static bool attr_set = false;
    if (!attr_set) {
        cudaFuncSetAttribute(attn8,    cudaFuncAttributeMaxDynamicSharedMemorySize, ATTN_SMEM);
        cudaFuncSetAttribute(ffn_mma4, cudaFuncAttributeMaxDynamicSharedMemorySize, FFN_SMEM);
        attr_set = true;
    }

    split_all<<<1536, 256>>>(Wq, Wk, Wv, Wo, ff1w, ff2w);
    attn8<<<Bn / 16, 512, ATTN_SMEM>>>(x_anc, x_nei, ln1g, ln1b);
    ffn_mma4<<<Bn / 64, 512, FFN_SMEM>>>(ln2g, ln2b, ff1b, ff2b, out);
}

// round 10
// speedup vs baseline: 1.0740x; 1.0740x over previous
#include <cuda_runtime.h>
#include <math.h>
#include <stdint.h>

#define Bn 32768
#define Dn 256
#define KN 32
#define FFn 1024

// residual after attention
__device__ float g_x[Bn * Dn];
// frag-ordered pre-split tf32 weights: uint4 {hi(b0), lo(b0), hi(b1), lo(b1)}
__device__ uint4 g_wqf[32 * 32 * 32];
__device__ uint4 g_wof[32 * 32 * 32];
__device__ uint4 g_wkf[8 * 4 * 32 * 32];
__device__ uint4 g_wvf[8 * 32 * 4 * 32];
__device__ uint4 g_w1f[32 * 128 * 32];
__device__ uint4 g_w2f[128 * 32 * 32];

// ---- attn smem layout (floats); cS/uS and qS/oS aliased (R8 layout) ----
#define SM_H 0                 // [8][268]  LN1 rows
#define SM_QS 2144             // [8][268]  Q  (later: attn-out rows oS)
#define SM_C 4288              // [64][268] c rows a*8+h (later: u rows h*8+a)
#define SM_SS 21440            // [8*8][33] scores
#define SM_A4 23552            // [8][264]  attn as [a][k][h]
#define ATTN_SMEM (25664 * 4)  // 102,656 B -> 2 CTAs/SM

// ---- ffn smem (uint2 words), R8 version ----
#define FH_STRIDE 266
#define FA_STRIDE 522
#define FFN_SMEM ((32 * FH_STRIDE + 32 * FA_STRIDE) * 8)

__device__ __forceinline__ uint32_t f2tf(float f) {
    uint32_t u;
    asm("cvt.rna.tf32.f32 %0, %1;" : "=r"(u) : "f"(f));
    return u;
}

__device__ __forceinline__ void mma8(float* c, const uint32_t* a, const uint32_t* b) {
    asm volatile(
        "mma.sync.aligned.m16n8k8.row.col.f32.tf32.tf32.f32 "
        "{%0,%1,%2,%3}, {%4,%5,%6,%7}, {%8,%9}, {%0,%1,%2,%3};"
        : "+f"(c[0]), "+f"(c[1]), "+f"(c[2]), "+f"(c[3])
        : "r"(a[0]), "r"(a[1]), "r"(a[2]), "r"(a[3]), "r"(b[0]), "r"(b[1]));
}

__device__ __forceinline__ uint4 splitpair(float b0, float b1) {
    uint4 r;
    r.x = f2tf(b0); r.y = f2tf(b0 - __uint_as_float(r.x));
    r.z = f2tf(b1); r.w = f2tf(b1 - __uint_as_float(r.z));
    return r;
}

// ---------------------------------------------------------------------------
__global__ void split_all(
    const float* __restrict__ Wq, const float* __restrict__ Wk,
    const float* __restrict__ Wv, const float* __restrict__ Wo,
    const float* __restrict__ ff1w, const float* __restrict__ ff2w)
{
    int gid = blockIdx.x * 256 + threadIdx.x;
    if (gid < 32768) {                                    // Wq
        int lane = gid & 31, t = gid >> 5;
        int ntile = t & 31, ks = t >> 5;
        int lg = lane >> 2, lc = lane & 3;
        int k0 = ks * 8 + lc, n = ntile * 8 + lg;
        g_wqf[gid] = splitpair(Wq[k0 * 256 + n], Wq[(k0 + 4) * 256 + n]);
    } else if (gid < 65536) {                             // Wo
        int e = gid - 32768;
        int lane = e & 31, t = e >> 5;
        int ntile = t & 31, ks = t >> 5;
        int lg = lane >> 2, lc = lane & 3;
        int k0 = ks * 8 + lc, n = ntile * 8 + lg;
        g_wof[e] = splitpair(Wo[k0 * 256 + n], Wo[(k0 + 4) * 256 + n]);
    } else if (gid < 98304) {                             // Wk per head (transposed)
        int e = gid - 65536;
        int lane = e & 31, t = e >> 5;
        int ntile = t & 31, hk = t >> 5;
        int h = hk >> 2, ks = hk & 3;
        int lg = lane >> 2, lc = lane & 3;
        int k0 = ks * 8 + lc, n = ntile * 8 + lg;
        g_wkf[e] = splitpair(Wk[n * 256 + h * 32 + k0],
                             Wk[n * 256 + h * 32 + k0 + 4]);
    } else if (gid < 229376) {                            // ff1w
        int e = gid - 98304;
        int lane = e & 31, t = e >> 5;
        int ntile = t & 127, ks = t >> 7;
        int lg = lane >> 2, lc = lane & 3;
        int k0 = ks * 8 + lc, n = ntile * 8 + lg;
        g_w1f[e] = splitpair(ff1w[k0 * FFn + n], ff1w[(k0 + 4) * FFn + n]);
    } else if (gid < 360448) {                            // ff2w
        int e = gid - 229376;
        int lane = e & 31, t = e >> 5;
        int ntile = t & 31, ks = t >> 5;
        int lg = lane >> 2, lc = lane & 3;
        int k0 = ks * 8 + lc, n = ntile * 8 + lg;
        g_w2f[e] = splitpair(ff2w[k0 * 256 + n], ff2w[(k0 + 4) * 256 + n]);
    } else if (gid < 393216) {                            // Wv per head
        int e = gid - 360448;
        int lane = e & 31, t = e >> 5;        // t in [0,1024)
        int nt = t & 3;
        int u2 = t >> 2;                      // [0,256)
        int ks = u2 & 31, hd = u2 >> 5;
        int lg = lane >> 2, lc = lane & 3;
        int k0 = ks * 8 + lc, n = hd * 32 + nt * 8 + lg;
        g_wvf[e] = splitpair(Wv[k0 * 256 + n], Wv[(k0 + 4) * 256 + n]);
    }
}

// ---------------------------------------------------------------------------
// Attention (R8 base): 8 anchors / CTA, 512 threads, 2 CTAs/SM.
// LN1 -> Q(mma) -> c(mma) -> scores -> softmax -> u -> Wv(mma) -> Wo(mma).
// ---------------------------------------------------------------------------
__global__ __launch_bounds__(512, 2) void attn9(
    const float* __restrict__ x_anc, const float* __restrict__ x_nei,
    const float* __restrict__ g1, const float* __restrict__ b1)
{
    extern __shared__ float sf[];
    float* hS  = sf + SM_H;
    float* qS  = sf + SM_QS;     // later oS
    float* cS  = sf + SM_C;      // later uS (rows h*8+a)
    float* sS  = sf + SM_SS;
    float* aS4 = sf + SM_A4;
    float* uS  = cS;
    float* oS  = qS;

    const int tid = threadIdx.x, wid = tid >> 5, lane = tid & 31;
    const int lg = lane >> 2, lc = lane & 3;
    const int j2 = tid & 255;
    const int b0 = blockIdx.x * 8;

    // ---- LN1: warps 0-7, one row each ----
    if (wid < 8) {
        const float* xr = x_anc + (size_t)(b0 + wid) * Dn;
        float4 v0 = *(const float4*)&xr[lane * 8];
        float4 v1 = *(const float4*)&xr[lane * 8 + 4];
        float v[8] = {v0.x, v0.y, v0.z, v0.w, v1.x, v1.y, v1.z, v1.w};
        float s = 0.f, s2 = 0.f;
        #pragma unroll
        for (int t = 0; t < 8; t++) { s += v[t]; s2 += v[t] * v[t]; }
        #pragma unroll
        for (int o = 16; o; o >>= 1) {
            s  += __shfl_xor_sync(0xffffffffu, s,  o);
            s2 += __shfl_xor_sync(0xffffffffu, s2, o);
        }
        const float mu   = s * (1.0f / Dn);
        const float var  = s2 * (1.0f / Dn) - mu * mu;
        const float rstd = rsqrtf(var + 1e-5f);
        #pragma unroll
        for (int t = 0; t < 8; t++) {
            const int c = lane * 8 + t;
            hS[wid * 268 + c] = (v[t] - mu) * rstd * g1[c] + b1[c];
        }
    }
    __syncthreads();

    // ---- Q = h @ Wq via mma (M=8 in frag rows lg; rows 8-15 zero) ----
    {
        float acc[2][4] = {{0.f,0.f,0.f,0.f},{0.f,0.f,0.f,0.f}};
        for (int ks = 0; ks < 32; ks++) {
            const int kb = ks * 8;
            float q0 = hS[lg * 268 + kb + lc];
            float q1 = hS[lg * 268 + kb + lc + 4];
            uint32_t ahi[4], alo[4];
            ahi[0] = f2tf(q0); alo[0] = f2tf(q0 - __uint_as_float(ahi[0]));
            ahi[2] = f2tf(q1); alo[2] = f2tf(q1 - __uint_as_float(ahi[2]));
            ahi[1] = alo[1] = ahi[3] = alo[3] = 0u;
            #pragma unroll
            for (int nt = 0; nt < 2; nt++) {
                uint4 v = g_wqf[(ks * 32 + wid * 2 + nt) * 32 + lane];
                uint32_t bhi[2] = {v.x, v.z}, blo[2] = {v.y, v.w};
                mma8(acc[nt], alo, bhi);
                mma8(acc[nt], ahi, blo);
                mma8(acc[nt], ahi, bhi);
            }
        }
        __syncthreads();
        #pragma unroll
        for (int nt = 0; nt < 2; nt++) {
            const int col = wid * 16 + nt * 8 + lc * 2;
            qS[lg * 268 + col]     = acc[nt][0];
            qS[lg * 268 + col + 1] = acc[nt][1];
        }
    }
    __syncthreads();

    // ---- c[a][h][:] via mma per head ----
    {
        #pragma unroll
        for (int h = 0; h < 8; h++) {
            float acc[2][4] = {{0.f,0.f,0.f,0.f},{0.f,0.f,0.f,0.f}};
            #pragma unroll
            for (int ks = 0; ks < 4; ks++) {
                const int kb = h * 32 + ks * 8;
                float q0 = qS[lg * 268 + kb + lc];
                float q1 = qS[lg * 268 + kb + lc + 4];
                uint32_t ahi[4], alo[4];
                ahi[0] = f2tf(q0); alo[0] = f2tf(q0 - __uint_as_float(ahi[0]));
                ahi[2] = f2tf(q1); alo[2] = f2tf(q1 - __uint_as_float(ahi[2]));
                ahi[1] = alo[1] = ahi[3] = alo[3] = 0u;
                #pragma unroll
                for (int nt = 0; nt < 2; nt++) {
                    uint4 v = g_wkf[((h * 4 + ks) * 32 + wid * 2 + nt) * 32 + lane];
                    uint32_t bhi[2] = {v.x, v.z}, blo[2] = {v.y, v.w};
                    mma8(acc[nt], alo, bhi);
                    mma8(acc[nt], ahi, blo);
                    mma8(acc[nt], ahi, bhi);
                }
            }
            #pragma unroll
            for (int nt = 0; nt < 2; nt++) {
                const int col = wid * 16 + nt * 8 + lc * 2;
                cS[(lg * 8 + h) * 268 + col]     = acc[nt][0];
                cS[(lg * 8 + h) * 268 + col + 1] = acc[nt][1];
            }
        }
    }
    __syncthreads();

    // ---- scores (R8): warp-pair = anchor; kk2 = t6>>1, ss2 = t6&1 ----
    {
        const int t6 = tid & 63;
        const int aa = tid >> 6;
        const int kk2 = t6 >> 1;
        const int ss2 = t6 & 1;
        const float* xb = x_nei + (size_t)(b0 + aa) * (KN * Dn) + kk2 * Dn;

        float pr[8];
        #pragma unroll
        for (int h = 0; h < 8; h++) pr[h] = 0.f;
        #pragma unroll
        for (int i = 0; i < 32; i++) {
            float4 x4 = *(const float4*)&xb[ss2 * 4 + i * 8];
            #pragma unroll
            for (int h = 0; h < 8; h++) {
                float4 c4 = *(const float4*)&cS[(aa * 8 + h) * 268 + ss2 * 4 + i * 8];
                pr[h] = fmaf(x4.x, c4.x, fmaf(x4.y, c4.y,
                        fmaf(x4.z, c4.z, fmaf(x4.w, c4.w, pr[h]))));
            }
        }
        #pragma unroll
        for (int h = 0; h < 8; h++)
            pr[h] += __shfl_xor_sync(0xffffffffu, pr[h], 1);
        #pragma unroll
        for (int t = 0; t < 4; t++) {
            const int h = ss2 * 4 + t;
            sS[(aa * 8 + h) * 33 + kk2] = pr[h];
        }
    }
    __syncthreads();

    // ---- softmax: warp handles 4 (a,h) rows; write aS4[a][k][h] ----
    {
        #pragma unroll
        for (int rr = 0; rr < 4; rr++) {
            const int r = wid * 4 + rr;
            const int a = r >> 3, h = r & 7;
            float sc = sS[r * 33 + lane] * 0.17677669529663687f;
            float m = sc;
            #pragma unroll
            for (int o = 16; o; o >>= 1)
                m = fmaxf(m, __shfl_xor_sync(0xffffffffu, m, o));
            float e = expf(sc - m), es = e;
            #pragma unroll
            for (int o = 16; o; o >>= 1)
                es += __shfl_xor_sync(0xffffffffu, es, o);
            aS4[a * 264 + lane * 8 + h] = e / es;
        }
    }
    __syncthreads();

    // ---- u: thread j2 covers col j2 for 4 anchors; uS rows = h*8+a ----
    {
        const int a0g = (tid >> 8) * 4;
        #pragma unroll
        for (int a = 0; a < 4; a++) {
            const int ag = a0g + a;
            const float* xb = x_nei + (size_t)(b0 + ag) * (KN * Dn) + j2;
            float u[8] = {0.f,0.f,0.f,0.f,0.f,0.f,0.f,0.f};
            #pragma unroll
            for (int k = 0; k < 32; k++) {
                float xv = xb[k * Dn];
                float4 af0 = *(const float4*)&aS4[ag * 264 + k * 8];
                float4 af1 = *(const float4*)&aS4[ag * 264 + k * 8 + 4];
                u[0] = fmaf(af0.x, xv, u[0]);
                u[1] = fmaf(af0.y, xv, u[1]);
                u[2] = fmaf(af0.z, xv, u[2]);
                u[3] = fmaf(af0.w, xv, u[3]);
                u[4] = fmaf(af1.x, xv, u[4]);
                u[5] = fmaf(af1.y, xv, u[5]);
                u[6] = fmaf(af1.z, xv, u[6]);
                u[7] = fmaf(af1.w, xv, u[7]);
            }
            #pragma unroll
            for (int h = 0; h < 8; h++)
                uS[(h * 8 + ag) * 268 + j2] = u[h];
        }
    }
    __syncthreads();

    // ---- Wv via mma per head; warp-pair shares a head (A-frags loaded once) ----
    {
        const int hd = wid >> 1;                  // head for this warp
        const int ntb = (wid & 1) * 2;            // N-units: ntb, ntb+1
        float acc[2][4] = {{0.f,0.f,0.f,0.f},{0.f,0.f,0.f,0.f}};
        for (int ks = 0; ks < 32; ks++) {
            const int kb = ks * 8;
            float f0 = uS[(hd * 8 + lg) * 268 + kb + lc];
            float f2 = uS[(hd * 8 + lg) * 268 + kb + lc + 4];
            uint32_t ahi[4], alo[4];
            ahi[0] = f2tf(f0); alo[0] = f2tf(f0 - __uint_as_float(ahi[0]));
            ahi[2] = f2tf(f2); alo[2] = f2tf(f2 - __uint_as_float(ahi[2]));
            ahi[1] = alo[1] = ahi[3] = alo[3] = 0u;
            #pragma unroll
            for (int uu = 0; uu < 2; uu++) {
                const int nt = ntb + uu;
                uint4 v = g_wvf[((hd * 32 + ks) * 4 + nt) * 32 + lane];
                uint32_t bhi[2] = {v.x, v.z}, blo[2] = {v.y, v.w};
                mma8(acc[uu], alo, bhi);
                mma8(acc[uu], ahi, blo);
                mma8(acc[uu], ahi, bhi);
            }
        }
        __syncthreads();    // oS aliases qS; ensure c-phase reads done (long past)
        #pragma unroll
        for (int uu = 0; uu < 2; uu++) {
            const int col = hd * 32 + (ntb + uu) * 8 + lc * 2;
            oS[lg * 268 + col]     = acc[uu][0];
            oS[lg * 268 + col + 1] = acc[uu][1];
        }
    }
    __syncthreads();

    // ---- x = x_anc + oS @ Wo via mma ----
    {
        float acc[2][4] = {{0.f,0.f,0.f,0.f},{0.f,0.f,0.f,0.f}};
        for (int ks = 0; ks < 32; ks++) {
            const int kb = ks * 8;
            float q0 = oS[lg * 268 + kb + lc];
            float q1 = oS[lg * 268 + kb + lc + 4];
            uint32_t ahi[4], alo[4];
            ahi[0] = f2tf(q0); alo[0] = f2tf(q0 - __uint_as_float(ahi[0]));
            ahi[2] = f2tf(q1); alo[2] = f2tf(q1 - __uint_as_float(ahi[2]));
            ahi[1] = alo[1] = ahi[3] = alo[3] = 0u;
            #pragma unroll
            for (int nt = 0; nt < 2; nt++) {
                uint4 v = g_wof[(ks * 32 + wid * 2 + nt) * 32 + lane];
                uint32_t bhi[2] = {v.x, v.z}, blo[2] = {v.y, v.w};
                mma8(acc[nt], alo, bhi);
                mma8(acc[nt], ahi, blo);
                mma8(acc[nt], ahi, bhi);
            }
        }
        #pragma unroll
        for (int nt = 0; nt < 2; nt++) {
            const int col = wid * 16 + nt * 8 + lc * 2;
            const size_t idx = (size_t)(b0 + lg) * Dn + col;
            g_x[idx]     = x_anc[idx]     + acc[nt][0];
            g_x[idx + 1] = x_anc[idx + 1] + acc[nt][1];
        }
    }
}

// ---------------------------------------------------------------------------
// FFN (R8 ffn_mma3, unchanged): LN2 -> ff1(mma)+gelu -> ff2(mma)+residual.
// ---------------------------------------------------------------------------
__global__ __launch_bounds__(512, 1) void ffn_mma3(
    const float* __restrict__ ln2g, const float* __restrict__ ln2b,
    const float* __restrict__ ff1b, const float* __restrict__ ff2b,
    float* __restrict__ out)
{
    extern __shared__ uint2 su[];
    uint2* hHL   = su;
    uint2* actHL = su + 32 * FH_STRIDE;

    const int tid = threadIdx.x, wid = tid >> 5, lane = tid & 31;
    const int lg = lane >> 2, lc = lane & 3;
    const int row0 = blockIdx.x * 32;

    #pragma unroll
    for (int rr = 0; rr < 2; rr++) {
        const int row = wid * 2 + rr;
        const float* xr = g_x + (size_t)(row0 + row) * Dn;
        float4 v0 = *(const float4*)&xr[lane * 8];
        float4 v1 = *(const float4*)&xr[lane * 8 + 4];
        float v[8] = {v0.x, v0.y, v0.z, v0.w, v1.x, v1.y, v1.z, v1.w};
        float s = 0.f, s2 = 0.f;
        #pragma unroll
        for (int t = 0; t < 8; t++) { s += v[t]; s2 += v[t] * v[t]; }
        #pragma unroll
        for (int o = 16; o; o >>= 1) {
            s  += __shfl_xor_sync(0xffffffffu, s,  o);
            s2 += __shfl_xor_sync(0xffffffffu, s2, o);
        }
        const float mu   = s * (1.0f / Dn);
        const float var  = s2 * (1.0f / Dn) - mu * mu;
        const float rstd = rsqrtf(var + 1e-5f);
        #pragma unroll
        for (int t = 0; t < 8; t++) {
            const int c = lane * 8 + t;
            float hv = (v[t] - mu) * rstd * ln2g[c] + ln2b[c];
            uint32_t hi = f2tf(hv);
            hHL[row * FH_STRIDE + c] = make_uint2(hi, f2tf(hv - __uint_as_float(hi)));
        }
    }
    __syncthreads();

    float acc2[2][2][4];
    #pragma unroll
    for (int mt = 0; mt < 2; mt++)
        #pragma unroll
        for (int nt = 0; nt < 2; nt++)
            #pragma unroll
            for (int e = 0; e < 4; e++) acc2[mt][nt][e] = 0.f;

    for (int half = 0; half < 2; half++) {
        float acc[2][4][4];
        #pragma unroll
        for (int mt = 0; mt < 2; mt++)
            #pragma unroll
            for (int nt = 0; nt < 4; nt++)
                #pragma unroll
                for (int e = 0; e < 4; e++) acc[mt][nt][e] = 0.f;

        for (int ks = 0; ks < 32; ks++) {
            const int kb = ks * 8;
            uint32_t ahi[2][4], alo[2][4];
            #pragma unroll
            for (int mt = 0; mt < 2; mt++) {
                const int r0 = mt * 16 + lg;
                uint2 p0 = hHL[r0 * FH_STRIDE + kb + lc];
                uint2 p1 = hHL[(r0 + 8) * FH_STRIDE + kb + lc];
                uint2 p2 = hHL[r0 * FH_STRIDE + kb + lc + 4];
                uint2 p3 = hHL[(r0 + 8) * FH_STRIDE + kb + lc + 4];
                ahi[mt][0] = p0.x; alo[mt][0] = p0.y;
                ahi[mt][1] = p1.x; alo[mt][1] = p1.y;
                ahi[mt][2] = p2.x; alo[mt][2] = p2.y;
                ahi[mt][3] = p3.x; alo[mt][3] = p3.y;
            }
            #pragma unroll
            for (int nt = 0; nt < 4; nt++) {
                const int ntile = half * 64 + wid * 4 + nt;
                uint4 v = g_w1f[(ks * 128 + ntile) * 32 + lane];
                uint32_t bhi[2] = {v.x, v.z}, blo[2] = {v.y, v.w};
                #pragma unroll
                for (int mt = 0; mt < 2; mt++) {
                    mma8(acc[mt][nt], alo[mt], bhi);
                    mma8(acc[mt][nt], ahi[mt], blo);
                    mma8(acc[mt][nt], ahi[mt], bhi);
                }
            }
        }

        #pragma unroll
        for (int mt = 0; mt < 2; mt++) {
            const int r0 = mt * 16 + lg;
            #pragma unroll
            for (int nt = 0; nt < 4; nt++) {
                const int lcol = wid * 32 + nt * 8 + lc * 2;
                const int gcol = half * 512 + lcol;
                #pragma unroll
                for (int e = 0; e < 2; e++) {
                    const float bb = ff1b[gcol + e];
                    float u0 = acc[mt][nt][e] + bb;
                    float u1 = acc[mt][nt][2 + e] + bb;
                    float g0 = 0.5f * u0 * (1.0f + erff(u0 * 0.70710678118654752f));
                    float g1v = 0.5f * u1 * (1.0f + erff(u1 * 0.70710678118654752f));
                    uint32_t h0 = f2tf(g0), h1 = f2tf(g1v);
                    actHL[r0 * FA_STRIDE + lcol + e] =
                        make_uint2(h0, f2tf(g0 - __uint_as_float(h0)));
                    actHL[(r0 + 8) * FA_STRIDE + lcol + e] =
                        make_uint2(h1, f2tf(g1v - __uint_as_float(h1)));
                }
            }
        }
        __syncthreads();

        for (int ks = 0; ks < 64; ks++) {
            const int kb = ks * 8;
            uint32_t ahi[2][4], alo[2][4];
            #pragma unroll
            for (int mt = 0; mt < 2; mt++) {
                const int r0 = mt * 16 + lg;
                uint2 p0 = actHL[r0 * FA_STRIDE + kb + lc];
                uint2 p1 = actHL[(r0 + 8) * FA_STRIDE + kb + lc];
                uint2 p2 = actHL[r0 * FA_STRIDE + kb + lc + 4];
                uint2 p3 = actHL[(r0 + 8) * FA_STRIDE + kb + lc + 4];
                ahi[mt][0] = p0.x; alo[mt][0] = p0.y;
                ahi[mt][1] = p1.x; alo[mt][1] = p1.y;
                ahi[mt][2] = p2.x; alo[mt][2] = p2.y;
                ahi[mt][3] = p3.x; alo[mt][3] = p3.y;
            }
            #pragma unroll
            for (int nt = 0; nt < 2; nt++) {
                const int ntile = wid * 2 + nt;
                const int ksg = half * 64 + ks;
                uint4 v = g_w2f[(ksg * 32 + ntile) * 32 + lane];
                uint32_t bhi[2] = {v.x, v.z}, blo[2] = {v.y, v.w};
                #pragma unroll
                for (int mt = 0; mt < 2; mt++) {
                    mma8(acc2[mt][nt], alo[mt], bhi);
                    mma8(acc2[mt][nt], ahi[mt], blo);
                    mma8(acc2[mt][nt], ahi[mt], bhi);
                }
            }
        }
        __syncthreads();
    }

    #pragma unroll
    for (int mt = 0; mt < 2; mt++) {
        const int r0 = mt * 16 + lg;
        #pragma unroll
        for (int nt = 0; nt < 2; nt++) {
            const int col = wid * 16 + nt * 8 + lc * 2;
            const float b0 = ff2b[col], b1 = ff2b[col + 1];
            const size_t i0 = (size_t)(row0 + r0) * Dn + col;
            const size_t i1 = (size_t)(row0 + r0 + 8) * Dn + col;
            out[i0]     = g_x[i0]     + acc2[mt][nt][0] + b0;
            out[i0 + 1] = g_x[i0 + 1] + acc2[mt][nt][1] + b1;
            out[i1]     = g_x[i1]     + acc2[mt][nt][2] + b0;
            out[i1 + 1] = g_x[i1 + 1] + acc2[mt][nt][3] + b1;
        }
    }
}

extern "C" void kernel_launch(void* const* d_in, const int* in_sizes, int n_in,
                              void* d_out, int out_size)
{
    const float* x_anc = (const float*)d_in[0];
    const float* x_nei = (const float*)d_in[1];
    const float* Wq    = (const float*)d_in[2];
    const float* Wk    = (const float*)d_in[3];
    const float* Wv    = (const float*)d_in[4];
    const float* Wo    = (const float*)d_in[5];
    const float* ln1g  = (const float*)d_in[6];
    const float* ln1b  = (const float*)d_in[7];
    const float* ln2g  = (const float*)d_in[8];
    const float* ln2b  = (const float*)d_in[9];
    const float* ff1w  = (const float*)d_in[10];
    const float* ff1b  = (const float*)d_in[11];
    const float* ff2w  = (const float*)d_in[12];
    const float* ff2b  = (const float*)d_in[13];
    float* out = (float*)d_out;

    static bool attr_set = false;
    if (!attr_set) {
        cudaFuncSetAttribute(attn9,    cudaFuncAttributeMaxDynamicSharedMemorySize, ATTN_SMEM);
        cudaFuncSetAttribute(ffn_mma3, cudaFuncAttributeMaxDynamicSharedMemorySize, FFN_SMEM);
        attr_set = true;
    }

    split_all<<<1536, 256>>>(Wq, Wk, Wv, Wo, ff1w, ff2w);
    attn9<<<Bn / 8, 512, ATTN_SMEM>>>(x_anc, x_nei, ln1g, ln1b);
    ffn_mma3<<<Bn / 32, 512, FFN_SMEM>>>(ln2g, ln2b, ff1b, ff2b, out);
}

// round 11
// speedup vs baseline: 1.5644x; 1.4566x over previous
#include <cuda_runtime.h>
#include <cuda_bf16.h>
#include <math.h>
#include <stdint.h>

#define Bn 32768
#define Dn 256
#define KN 32
#define FFn 1024

// residual after attention
__device__ float g_x[Bn * Dn];
// frag-ordered pre-split bf16 weights: uint4 {bhi0, blo0, bhi1, blo1}
// (each uint4 covers k = {2lc, 2lc+1, 2lc+8, 2lc+9} at one column)
__device__ uint4 g_wqf[16 * 32 * 32];
__device__ uint4 g_wof[16 * 32 * 32];
__device__ uint4 g_wkf[8 * 2 * 32 * 32];
__device__ uint4 g_wvf[8 * 16 * 4 * 32];
__device__ uint4 g_w1f[16 * 128 * 32];
__device__ uint4 g_w2f[64 * 32 * 32];

// ---- attn smem layout (floats); cS/uS and qS/oS aliased (R10 layout) ----
#define SM_H 0                 // [8][268]  LN1 rows
#define SM_QS 2144             // [8][268]  Q  (later: attn-out rows oS)
#define SM_C 4288              // [64][268] c rows a*8+h (later: u rows h*8+a)
#define SM_SS 21440            // [8*8][33] scores
#define SM_A4 23552            // [8][264]  attn as [a][k][h]
#define ATTN_SMEM (25664 * 4)  // 102,656 B -> 2 CTAs/SM

// ---- ffn smem (uint2 = packed {hi_pair, lo_pair}) ----
#define FH2 134                // hHL [32][134] pairs (128 + pad)
#define FA2 262                // act [32][262] pairs (256 + pad)
#define FFN_SMEM ((32 * FH2 + 32 * FA2) * 8)

__device__ __forceinline__ void mmabf(float* c, const uint32_t* a, const uint32_t* b) {
    asm volatile(
        "mma.sync.aligned.m16n8k16.row.col.f32.bf16.bf16.f32 "
        "{%0,%1,%2,%3}, {%4,%5,%6,%7}, {%8,%9}, {%0,%1,%2,%3};"
        : "+f"(c[0]), "+f"(c[1]), "+f"(c[2]), "+f"(c[3])
        : "r"(a[0]), "r"(a[1]), "r"(a[2]), "r"(a[3]), "r"(b[0]), "r"(b[1]));
}

// split two floats into packed bf16x2 {hi, lo} (elem0 in lower half)
__device__ __forceinline__ uint2 bsplit2(float x, float y) {
    __nv_bfloat16 hx = __float2bfloat16(x), hy = __float2bfloat16(y);
    float rx = x - __bfloat162float(hx), ry = y - __bfloat162float(hy);
    __nv_bfloat16 lx = __float2bfloat16(rx), ly = __float2bfloat16(ry);
    uint2 r;
    r.x = ((uint32_t)__bfloat16_as_ushort(hy) << 16) | __bfloat16_as_ushort(hx);
    r.y = ((uint32_t)__bfloat16_as_ushort(ly) << 16) | __bfloat16_as_ushort(lx);
    return r;
}

__device__ __forceinline__ void asplit(float f0, float f1, uint32_t& hi, uint32_t& lo) {
    uint2 p = bsplit2(f0, f1);
    hi = p.x; lo = p.y;
}

// ---------------------------------------------------------------------------
// setup: all frag-ordered bf16 hi/lo weight tables. 196608 gids.
// ---------------------------------------------------------------------------
__global__ void split_all(
    const float* __restrict__ Wq, const float* __restrict__ Wk,
    const float* __restrict__ Wv, const float* __restrict__ Wo,
    const float* __restrict__ ff1w, const float* __restrict__ ff2w)
{
    int gid = blockIdx.x * 256 + threadIdx.x;
    int lane, lg, lc;
    if (gid < 16384) {                                    // Wq: [ks16][nt32][lane]
        int e = gid;
        lane = e & 31; lg = lane >> 2; lc = lane & 3;
        int t = e >> 5, ntile = t & 31, ks = t >> 5;
        int k0 = ks * 16 + 2 * lc, n = ntile * 8 + lg;
        uint2 p0 = bsplit2(Wq[k0 * 256 + n], Wq[(k0 + 1) * 256 + n]);
        uint2 p1 = bsplit2(Wq[(k0 + 8) * 256 + n], Wq[(k0 + 9) * 256 + n]);
        g_wqf[e] = make_uint4(p0.x, p0.y, p1.x, p1.y);
    } else if (gid < 32768) {                             // Wo
        int e = gid - 16384;
        lane = e & 31; lg = lane >> 2; lc = lane & 3;
        int t = e >> 5, ntile = t & 31, ks = t >> 5;
        int k0 = ks * 16 + 2 * lc, n = ntile * 8 + lg;
        uint2 p0 = bsplit2(Wo[k0 * 256 + n], Wo[(k0 + 1) * 256 + n]);
        uint2 p1 = bsplit2(Wo[(k0 + 8) * 256 + n], Wo[(k0 + 9) * 256 + n]);
        g_wof[e] = make_uint4(p0.x, p0.y, p1.x, p1.y);
    } else if (gid < 49152) {                             // Wk per head: [h][ks2][nt32][lane]
        int e = gid - 32768;
        lane = e & 31; lg = lane >> 2; lc = lane & 3;
        int t = e >> 5, ntile = t & 31, hk = t >> 5;      // hk = h*2 + ks2
        int h = hk >> 1, ks2 = hk & 1;
        int k0 = ks2 * 16 + 2 * lc, n = ntile * 8 + lg;
        const float* base = Wk + n * 256 + h * 32;
        uint2 p0 = bsplit2(base[k0], base[k0 + 1]);
        uint2 p1 = bsplit2(base[k0 + 8], base[k0 + 9]);
        g_wkf[e] = make_uint4(p0.x, p0.y, p1.x, p1.y);
    } else if (gid < 65536) {                             // Wv: [hd][ks16][nt4][lane]
        int e = gid - 49152;
        lane = e & 31; lg = lane >> 2; lc = lane & 3;
        int t = e >> 5, nt = t & 3, u2 = t >> 2;
        int ks = u2 & 15, hd = u2 >> 4;
        int k0 = ks * 16 + 2 * lc, n = hd * 32 + nt * 8 + lg;
        uint2 p0 = bsplit2(Wv[k0 * 256 + n], Wv[(k0 + 1) * 256 + n]);
        uint2 p1 = bsplit2(Wv[(k0 + 8) * 256 + n], Wv[(k0 + 9) * 256 + n]);
        g_wvf[e] = make_uint4(p0.x, p0.y, p1.x, p1.y);
    } else if (gid < 131072) {                            // ff1w: [ks16][nt128][lane]
        int e = gid - 65536;
        lane = e & 31; lg = lane >> 2; lc = lane & 3;
        int t = e >> 5, ntile = t & 127, ks = t >> 7;
        int k0 = ks * 16 + 2 * lc, n = ntile * 8 + lg;
        uint2 p0 = bsplit2(ff1w[k0 * FFn + n], ff1w[(k0 + 1) * FFn + n]);
        uint2 p1 = bsplit2(ff1w[(k0 + 8) * FFn + n], ff1w[(k0 + 9) * FFn + n]);
        g_w1f[e] = make_uint4(p0.x, p0.y, p1.x, p1.y);
    } else if (gid < 196608) {                            // ff2w: [ks64][nt32][lane]
        int e = gid - 131072;
        lane = e & 31; lg = lane >> 2; lc = lane & 3;
        int t = e >> 5, ntile = t & 31, ks = t >> 5;
        int k0 = ks * 16 + 2 * lc, n = ntile * 8 + lg;
        uint2 p0 = bsplit2(ff2w[k0 * 256 + n], ff2w[(k0 + 1) * 256 + n]);
        uint2 p1 = bsplit2(ff2w[(k0 + 8) * 256 + n], ff2w[(k0 + 9) * 256 + n]);
        g_w2f[e] = make_uint4(p0.x, p0.y, p1.x, p1.y);
    }
}

// ---------------------------------------------------------------------------
// Attention (bf16 mma): 8 anchors / CTA, 512 threads, 2 CTAs/SM.
// ---------------------------------------------------------------------------
__global__ __launch_bounds__(512, 2) void attn10(
    const float* __restrict__ x_anc, const float* __restrict__ x_nei,
    const float* __restrict__ g1, const float* __restrict__ b1)
{
    extern __shared__ float sf[];
    float* hS  = sf + SM_H;
    float* qS  = sf + SM_QS;     // later oS
    float* cS  = sf + SM_C;      // later uS (rows h*8+a)
    float* sS  = sf + SM_SS;
    float* aS4 = sf + SM_A4;
    float* uS  = cS;
    float* oS  = qS;

    const int tid = threadIdx.x, wid = tid >> 5, lane = tid & 31;
    const int lg = lane >> 2, lc = lane & 3;
    const int j2 = tid & 255;
    const int b0 = blockIdx.x * 8;

    // ---- LN1 ----
    if (wid < 8) {
        const float* xr = x_anc + (size_t)(b0 + wid) * Dn;
        float4 v0 = *(const float4*)&xr[lane * 8];
        float4 v1 = *(const float4*)&xr[lane * 8 + 4];
        float v[8] = {v0.x, v0.y, v0.z, v0.w, v1.x, v1.y, v1.z, v1.w};
        float s = 0.f, s2 = 0.f;
        #pragma unroll
        for (int t = 0; t < 8; t++) { s += v[t]; s2 += v[t] * v[t]; }
        #pragma unroll
        for (int o = 16; o; o >>= 1) {
            s  += __shfl_xor_sync(0xffffffffu, s,  o);
            s2 += __shfl_xor_sync(0xffffffffu, s2, o);
        }
        const float mu   = s * (1.0f / Dn);
        const float var  = s2 * (1.0f / Dn) - mu * mu;
        const float rstd = rsqrtf(var + 1e-5f);
        #pragma unroll
        for (int t = 0; t < 8; t++) {
            const int c = lane * 8 + t;
            hS[wid * 268 + c] = (v[t] - mu) * rstd * g1[c] + b1[c];
        }
    }
    __syncthreads();

    // ---- Q = h @ Wq (bf16 mma, M=8) ----
    {
        float acc[2][4] = {{0.f,0.f,0.f,0.f},{0.f,0.f,0.f,0.f}};
        #pragma unroll
        for (int ks = 0; ks < 16; ks++) {
            const int kb = ks * 16;
            float2 p0 = *(const float2*)&hS[lg * 268 + kb + 2 * lc];
            float2 p1 = *(const float2*)&hS[lg * 268 + kb + 8 + 2 * lc];
            uint32_t Ah[4], Al[4];
            asplit(p0.x, p0.y, Ah[0], Al[0]);
            asplit(p1.x, p1.y, Ah[2], Al[2]);
            Ah[1] = Al[1] = Ah[3] = Al[3] = 0u;
            #pragma unroll
            for (int nt = 0; nt < 2; nt++) {
                uint4 v = g_wqf[(ks * 32 + wid * 2 + nt) * 32 + lane];
                uint32_t bh[2] = {v.x, v.z}, bl[2] = {v.y, v.w};
                mmabf(acc[nt], Ah, bh);
                mmabf(acc[nt], Ah, bl);
                mmabf(acc[nt], Al, bh);
            }
        }
        __syncthreads();
        #pragma unroll
        for (int nt = 0; nt < 2; nt++) {
            const int col = wid * 16 + nt * 8 + lc * 2;
            qS[lg * 268 + col]     = acc[nt][0];
            qS[lg * 268 + col + 1] = acc[nt][1];
        }
    }
    __syncthreads();

    // ---- c[a][h][:] (bf16 mma per head, K=32) ----
    {
        #pragma unroll
        for (int h = 0; h < 8; h++) {
            float acc[2][4] = {{0.f,0.f,0.f,0.f},{0.f,0.f,0.f,0.f}};
            #pragma unroll
            for (int ks2 = 0; ks2 < 2; ks2++) {
                const int kb = h * 32 + ks2 * 16;
                float2 p0 = *(const float2*)&qS[lg * 268 + kb + 2 * lc];
                float2 p1 = *(const float2*)&qS[lg * 268 + kb + 8 + 2 * lc];
                uint32_t Ah[4], Al[4];
                asplit(p0.x, p0.y, Ah[0], Al[0]);
                asplit(p1.x, p1.y, Ah[2], Al[2]);
                Ah[1] = Al[1] = Ah[3] = Al[3] = 0u;
                #pragma unroll
                for (int nt = 0; nt < 2; nt++) {
                    uint4 v = g_wkf[((h * 2 + ks2) * 32 + wid * 2 + nt) * 32 + lane];
                    uint32_t bh[2] = {v.x, v.z}, bl[2] = {v.y, v.w};
                    mmabf(acc[nt], Ah, bh);
                    mmabf(acc[nt], Ah, bl);
                    mmabf(acc[nt], Al, bh);
                }
            }
            #pragma unroll
            for (int nt = 0; nt < 2; nt++) {
                const int col = wid * 16 + nt * 8 + lc * 2;
                cS[(lg * 8 + h) * 268 + col]     = acc[nt][0];
                cS[(lg * 8 + h) * 268 + col + 1] = acc[nt][1];
            }
        }
    }
    __syncthreads();

    // ---- scores: warp-pair = anchor; kk2 = t6>>1, ss2 = t6&1 ----
    {
        const int t6 = tid & 63;
        const int aa = tid >> 6;
        const int kk2 = t6 >> 1;
        const int ss2 = t6 & 1;
        const float* xb = x_nei + (size_t)(b0 + aa) * (KN * Dn) + kk2 * Dn;

        float pr[8];
        #pragma unroll
        for (int h = 0; h < 8; h++) pr[h] = 0.f;
        #pragma unroll
        for (int i = 0; i < 32; i++) {
            float4 x4 = *(const float4*)&xb[ss2 * 4 + i * 8];
            #pragma unroll
            for (int h = 0; h < 8; h++) {
                float4 c4 = *(const float4*)&cS[(aa * 8 + h) * 268 + ss2 * 4 + i * 8];
                pr[h] = fmaf(x4.x, c4.x, fmaf(x4.y, c4.y,
                        fmaf(x4.z, c4.z, fmaf(x4.w, c4.w, pr[h]))));
            }
        }
        #pragma unroll
        for (int h = 0; h < 8; h++)
            pr[h] += __shfl_xor_sync(0xffffffffu, pr[h], 1);
        #pragma unroll
        for (int t = 0; t < 4; t++) {
            const int h = ss2 * 4 + t;
            sS[(aa * 8 + h) * 33 + kk2] = pr[h];
        }
    }
    __syncthreads();

    // ---- softmax -> aS4[a][k][h] ----
    {
        #pragma unroll
        for (int rr = 0; rr < 4; rr++) {
            const int r = wid * 4 + rr;
            const int a = r >> 3, h = r & 7;
            float sc = sS[r * 33 + lane] * 0.17677669529663687f;
            float m = sc;
            #pragma unroll
            for (int o = 16; o; o >>= 1)
                m = fmaxf(m, __shfl_xor_sync(0xffffffffu, m, o));
            float e = expf(sc - m), es = e;
            #pragma unroll
            for (int o = 16; o; o >>= 1)
                es += __shfl_xor_sync(0xffffffffu, es, o);
            aS4[a * 264 + lane * 8 + h] = e / es;
        }
    }
    __syncthreads();

    // ---- u: thread j2, 4 anchors; uS rows = h*8+a ----
    {
        const int a0g = (tid >> 8) * 4;
        #pragma unroll
        for (int a = 0; a < 4; a++) {
            const int ag = a0g + a;
            const float* xb = x_nei + (size_t)(b0 + ag) * (KN * Dn) + j2;
            float u[8] = {0.f,0.f,0.f,0.f,0.f,0.f,0.f,0.f};
            #pragma unroll
            for (int k = 0; k < 32; k++) {
                float xv = xb[k * Dn];
                float4 af0 = *(const float4*)&aS4[ag * 264 + k * 8];
                float4 af1 = *(const float4*)&aS4[ag * 264 + k * 8 + 4];
                u[0] = fmaf(af0.x, xv, u[0]);
                u[1] = fmaf(af0.y, xv, u[1]);
                u[2] = fmaf(af0.z, xv, u[2]);
                u[3] = fmaf(af0.w, xv, u[3]);
                u[4] = fmaf(af1.x, xv, u[4]);
                u[5] = fmaf(af1.y, xv, u[5]);
                u[6] = fmaf(af1.z, xv, u[6]);
                u[7] = fmaf(af1.w, xv, u[7]);
            }
            #pragma unroll
            for (int h = 0; h < 8; h++)
                uS[(h * 8 + ag) * 268 + j2] = u[h];
        }
    }
    __syncthreads();

    // ---- Wv (bf16 mma per head; warp-pair shares head) ----
    {
        const int hd = wid >> 1;
        const int ntb = (wid & 1) * 2;
        float acc[2][4] = {{0.f,0.f,0.f,0.f},{0.f,0.f,0.f,0.f}};
        #pragma unroll
        for (int ks = 0; ks < 16; ks++) {
            const int kb = ks * 16;
            float2 p0 = *(const float2*)&uS[(hd * 8 + lg) * 268 + kb + 2 * lc];
            float2 p1 = *(const float2*)&uS[(hd * 8 + lg) * 268 + kb + 8 + 2 * lc];
            uint32_t Ah[4], Al[4];
            asplit(p0.x, p0.y, Ah[0], Al[0]);
            asplit(p1.x, p1.y, Ah[2], Al[2]);
            Ah[1] = Al[1] = Ah[3] = Al[3] = 0u;
            #pragma unroll
            for (int uu = 0; uu < 2; uu++) {
                const int nt = ntb + uu;
                uint4 v = g_wvf[((hd * 16 + ks) * 4 + nt) * 32 + lane];
                uint32_t bh[2] = {v.x, v.z}, bl[2] = {v.y, v.w};
                mmabf(acc[uu], Ah, bh);
                mmabf(acc[uu], Ah, bl);
                mmabf(acc[uu], Al, bh);
            }
        }
        __syncthreads();
        #pragma unroll
        for (int uu = 0; uu < 2; uu++) {
            const int col = hd * 32 + (ntb + uu) * 8 + lc * 2;
            oS[lg * 268 + col]     = acc[uu][0];
            oS[lg * 268 + col + 1] = acc[uu][1];
        }
    }
    __syncthreads();

    // ---- x = x_anc + oS @ Wo (bf16 mma) ----
    {
        float acc[2][4] = {{0.f,0.f,0.f,0.f},{0.f,0.f,0.f,0.f}};
        #pragma unroll
        for (int ks = 0; ks < 16; ks++) {
            const int kb = ks * 16;
            float2 p0 = *(const float2*)&oS[lg * 268 + kb + 2 * lc];
            float2 p1 = *(const float2*)&oS[lg * 268 + kb + 8 + 2 * lc];
            uint32_t Ah[4], Al[4];
            asplit(p0.x, p0.y, Ah[0], Al[0]);
            asplit(p1.x, p1.y, Ah[2], Al[2]);
            Ah[1] = Al[1] = Ah[3] = Al[3] = 0u;
            #pragma unroll
            for (int nt = 0; nt < 2; nt++) {
                uint4 v = g_wof[(ks * 32 + wid * 2 + nt) * 32 + lane];
                uint32_t bh[2] = {v.x, v.z}, bl[2] = {v.y, v.w};
                mmabf(acc[nt], Ah, bh);
                mmabf(acc[nt], Ah, bl);
                mmabf(acc[nt], Al, bh);
            }
        }
        #pragma unroll
        for (int nt = 0; nt < 2; nt++) {
            const int col = wid * 16 + nt * 8 + lc * 2;
            const size_t idx = (size_t)(b0 + lg) * Dn + col;
            g_x[idx]     = x_anc[idx]     + acc[nt][0];
            g_x[idx + 1] = x_anc[idx + 1] + acc[nt][1];
        }
    }
}

// ---------------------------------------------------------------------------
// FFN (bf16 mma): 32 rows / CTA, 512 threads.
// ---------------------------------------------------------------------------
__global__ __launch_bounds__(512, 1) void ffn_bf(
    const float* __restrict__ ln2g, const float* __restrict__ ln2b,
    const float* __restrict__ ff1b, const float* __restrict__ ff2b,
    float* __restrict__ out)
{
    extern __shared__ uint2 su[];
    uint2* hHL = su;                      // [32][134] packed pairs
    uint2* act = su + 32 * FH2;           // [32][262] packed pairs

    const int tid = threadIdx.x, wid = tid >> 5, lane = tid & 31;
    const int lg = lane >> 2, lc = lane & 3;
    const int row0 = blockIdx.x * 32;

    // ---- LN2 -> packed split pairs ----
    #pragma unroll
    for (int rr = 0; rr < 2; rr++) {
        const int row = wid * 2 + rr;
        const float* xr = g_x + (size_t)(row0 + row) * Dn;
        float4 v0 = *(const float4*)&xr[lane * 8];
        float4 v1 = *(const float4*)&xr[lane * 8 + 4];
        float v[8] = {v0.x, v0.y, v0.z, v0.w, v1.x, v1.y, v1.z, v1.w};
        float s = 0.f, s2 = 0.f;
        #pragma unroll
        for (int t = 0; t < 8; t++) { s += v[t]; s2 += v[t] * v[t]; }
        #pragma unroll
        for (int o = 16; o; o >>= 1) {
            s  += __shfl_xor_sync(0xffffffffu, s,  o);
            s2 += __shfl_xor_sync(0xffffffffu, s2, o);
        }
        const float mu   = s * (1.0f / Dn);
        const float var  = s2 * (1.0f / Dn) - mu * mu;
        const float rstd = rsqrtf(var + 1e-5f);
        float hv[8];
        #pragma unroll
        for (int t = 0; t < 8; t++) {
            const int c = lane * 8 + t;
            hv[t] = (v[t] - mu) * rstd * ln2g[c] + ln2b[c];
        }
        #pragma unroll
        for (int t = 0; t < 4; t++)
            hHL[row * FH2 + lane * 4 + t] = bsplit2(hv[2 * t], hv[2 * t + 1]);
    }
    __syncthreads();

    float acc2[2][2][4];
    #pragma unroll
    for (int mt = 0; mt < 2; mt++)
        #pragma unroll
        for (int nt = 0; nt < 2; nt++)
            #pragma unroll
            for (int e = 0; e < 4; e++) acc2[mt][nt][e] = 0.f;

    for (int half = 0; half < 2; half++) {
        float acc[2][4][4];
        #pragma unroll
        for (int mt = 0; mt < 2; mt++)
            #pragma unroll
            for (int nt = 0; nt < 4; nt++)
                #pragma unroll
                for (int e = 0; e < 4; e++) acc[mt][nt][e] = 0.f;

        // ---- ff1: K=256 -> 16 ks16 ----
        #pragma unroll 4
        for (int ks = 0; ks < 16; ks++) {
            const int kb2 = ks * 8;
            uint32_t Ah[2][4], Al[2][4];
            #pragma unroll
            for (int mt = 0; mt < 2; mt++) {
                const int r0 = mt * 16 + lg;
                uint2 q0 = hHL[r0 * FH2 + kb2 + lc];
                uint2 q1 = hHL[(r0 + 8) * FH2 + kb2 + lc];
                uint2 q2 = hHL[r0 * FH2 + kb2 + 4 + lc];
                uint2 q3 = hHL[(r0 + 8) * FH2 + kb2 + 4 + lc];
                Ah[mt][0] = q0.x; Al[mt][0] = q0.y;
                Ah[mt][1] = q1.x; Al[mt][1] = q1.y;
                Ah[mt][2] = q2.x; Al[mt][2] = q2.y;
                Ah[mt][3] = q3.x; Al[mt][3] = q3.y;
            }
            #pragma unroll
            for (int nt = 0; nt < 4; nt++) {
                const int ntile = half * 64 + wid * 4 + nt;
                uint4 v = g_w1f[(ks * 128 + ntile) * 32 + lane];
                uint32_t bh[2] = {v.x, v.z}, bl[2] = {v.y, v.w};
                #pragma unroll
                for (int mt = 0; mt < 2; mt++) {
                    mmabf(acc[mt][nt], Ah[mt], bh);
                    mmabf(acc[mt][nt], Ah[mt], bl);
                    mmabf(acc[mt][nt], Al[mt], bh);
                }
            }
        }

        // ---- bias + gelu -> packed split act ----
        #pragma unroll
        for (int mt = 0; mt < 2; mt++) {
            const int r0 = mt * 16 + lg;
            #pragma unroll
            for (int nt = 0; nt < 4; nt++) {
                const int lcol = wid * 32 + nt * 8 + lc * 2;
                const int gcol = half * 512 + lcol;
                const float b0 = ff1b[gcol], b1 = ff1b[gcol + 1];
                float u0 = acc[mt][nt][0] + b0;
                float u1 = acc[mt][nt][1] + b1;
                float u2 = acc[mt][nt][2] + b0;
                float u3 = acc[mt][nt][3] + b1;
                float g0 = 0.5f * u0 * (1.0f + erff(u0 * 0.70710678118654752f));
                float g1v = 0.5f * u1 * (1.0f + erff(u1 * 0.70710678118654752f));
                float g2 = 0.5f * u2 * (1.0f + erff(u2 * 0.70710678118654752f));
                float g3 = 0.5f * u3 * (1.0f + erff(u3 * 0.70710678118654752f));
                const int pidx = lcol >> 1;      // = wid*16 + nt*4 + lc
                act[r0 * FA2 + pidx]       = bsplit2(g0, g1v);
                act[(r0 + 8) * FA2 + pidx] = bsplit2(g2, g3);
            }
        }
        __syncthreads();

        // ---- ff2 partial: this half's K=512 -> 32 ks16 ----
        #pragma unroll 4
        for (int ks = 0; ks < 32; ks++) {
            const int kb2 = ks * 8;
            uint32_t Ah[2][4], Al[2][4];
            #pragma unroll
            for (int mt = 0; mt < 2; mt++) {
                const int r0 = mt * 16 + lg;
                uint2 q0 = act[r0 * FA2 + kb2 + lc];
                uint2 q1 = act[(r0 + 8) * FA2 + kb2 + lc];
                uint2 q2 = act[r0 * FA2 + kb2 + 4 + lc];
                uint2 q3 = act[(r0 + 8) * FA2 + kb2 + 4 + lc];
                Ah[mt][0] = q0.x; Al[mt][0] = q0.y;
                Ah[mt][1] = q1.x; Al[mt][1] = q1.y;
                Ah[mt][2] = q2.x; Al[mt][2] = q2.y;
                Ah[mt][3] = q3.x; Al[mt][3] = q3.y;
            }
            const int ksg = half * 32 + ks;
            #pragma unroll
            for (int nt = 0; nt < 2; nt++) {
                const int ntile = wid * 2 + nt;
                uint4 v = g_w2f[(ksg * 32 + ntile) * 32 + lane];
                uint32_t bh[2] = {v.x, v.z}, bl[2] = {v.y, v.w};
                #pragma unroll
                for (int mt = 0; mt < 2; mt++) {
                    mmabf(acc2[mt][nt], Ah[mt], bh);
                    mmabf(acc2[mt][nt], Ah[mt], bl);
                    mmabf(acc2[mt][nt], Al[mt], bh);
                }
            }
        }
        __syncthreads();
    }

    // ---- epilogue: residual + ff2 bias ----
    #pragma unroll
    for (int mt = 0; mt < 2; mt++) {
        const int r0 = mt * 16 + lg;
        #pragma unroll
        for (int nt = 0; nt < 2; nt++) {
            const int col = wid * 16 + nt * 8 + lc * 2;
            const float b0 = ff2b[col], b1 = ff2b[col + 1];
            const size_t i0 = (size_t)(row0 + r0) * Dn + col;
            const size_t i1 = (size_t)(row0 + r0 + 8) * Dn + col;
            out[i0]     = g_x[i0]     + acc2[mt][nt][0] + b0;
            out[i0 + 1] = g_x[i0 + 1] + acc2[mt][nt][1] + b1;
            out[i1]     = g_x[i1]     + acc2[mt][nt][2] + b0;
            out[i1 + 1] = g_x[i1 + 1] + acc2[mt][nt][3] + b1;
        }
    }
}

extern "C" void kernel_launch(void* const* d_in, const int* in_sizes, int n_in,
                              void* d_out, int out_size)
{
    const float* x_anc = (const float*)d_in[0];
    const float* x_nei = (const float*)d_in[1];
    const float* Wq    = (const float*)d_in[2];
    const float* Wk    = (const float*)d_in[3];
    const float* Wv    = (const float*)d_in[4];
    const float* Wo    = (const float*)d_in[5];
    const float* ln1g  = (const float*)d_in[6];
    const float* ln1b  = (const float*)d_in[7];
    const float* ln2g  = (const float*)d_in[8];
    const float* ln2b  = (const float*)d_in[9];
    const float* ff1w  = (const float*)d_in[10];
    const float* ff1b  = (const float*)d_in[11];
    const float* ff2w  = (const float*)d_in[12];
    const float* ff2b  = (const float*)d_in[13];
    float* out = (float*)d_out;

    static bool attr_set = false;
    if (!attr_set) {
        cudaFuncSetAttribute(attn10, cudaFuncAttributeMaxDynamicSharedMemorySize, ATTN_SMEM);
        cudaFuncSetAttribute(ffn_bf, cudaFuncAttributeMaxDynamicSharedMemorySize, FFN_SMEM);
        attr_set = true;
    }

    split_all<<<768, 256>>>(Wq, Wk, Wv, Wo, ff1w, ff2w);
    attn10<<<Bn / 8, 512, ATTN_SMEM>>>(x_anc, x_nei, ln1g, ln1b);
    ffn_bf<<<Bn / 32, 512, FFN_SMEM>>>(ln2g, ln2b, ff1b, ff2b, out);
}

// round 12
// speedup vs baseline: 1.7334x; 1.1080x over previous
#include <cuda_runtime.h>
#include <cuda_bf16.h>
#include <math.h>
#include <stdint.h>

#define Bn 32768
#define Dn 256
#define KN 32
#define FFn 1024

// residual after attention
__device__ float g_x[Bn * Dn];
// frag-ordered pre-split bf16 weights: uint4 {bhi0, blo0, bhi1, blo1}
__device__ uint4 g_wqf[16 * 32 * 32];
__device__ uint4 g_wof[16 * 32 * 32];
__device__ uint4 g_wkf[8 * 2 * 32 * 32];
__device__ uint4 g_wvf[8 * 16 * 4 * 32];
__device__ uint4 g_w1f[16 * 128 * 32];
__device__ uint4 g_w2f[64 * 32 * 32];

// ---- attn smem layout (float offsets) ----
#define SM_H  0                // hS  [8][268]
#define SM_QS 2144             // qS  [8][268]  (later oS)
#define SM_CB 4288             // cB uint4 [8][16][32] (64KB)  -> later uB uint2 [64][130]
#define SM_SS 20928            // sS  [64][33]
#define SM_A4 23040            // aS4 [8][264]  attn as [a][k][h]
#define ATTN_SMEM (25152 * 4)  // 100,608 B -> 2 CTAs/SM

// ---- ffn smem (uint2 = packed {hi_pair, lo_pair}) ----
#define FH2 134
#define FA2 262
#define FFN_SMEM ((32 * FH2 + 32 * FA2) * 8)

__device__ __forceinline__ void mmabf(float* c, const uint32_t* a, const uint32_t* b) {
    asm volatile(
        "mma.sync.aligned.m16n8k16.row.col.f32.bf16.bf16.f32 "
        "{%0,%1,%2,%3}, {%4,%5,%6,%7}, {%8,%9}, {%0,%1,%2,%3};"
        : "+f"(c[0]), "+f"(c[1]), "+f"(c[2]), "+f"(c[3])
        : "r"(a[0]), "r"(a[1]), "r"(a[2]), "r"(a[3]), "r"(b[0]), "r"(b[1]));
}

__device__ __forceinline__ uint2 bsplit2(float x, float y) {
    __nv_bfloat16 hx = __float2bfloat16(x), hy = __float2bfloat16(y);
    float rx = x - __bfloat162float(hx), ry = y - __bfloat162float(hy);
    __nv_bfloat16 lx = __float2bfloat16(rx), ly = __float2bfloat16(ry);
    uint2 r;
    r.x = ((uint32_t)__bfloat16_as_ushort(hy) << 16) | __bfloat16_as_ushort(hx);
    r.y = ((uint32_t)__bfloat16_as_ushort(ly) << 16) | __bfloat16_as_ushort(lx);
    return r;
}

__device__ __forceinline__ void asplit(float f0, float f1, uint32_t& hi, uint32_t& lo) {
    uint2 p = bsplit2(f0, f1);
    hi = p.x; lo = p.y;
}

// ---------------------------------------------------------------------------
__global__ void split_all(
    const float* __restrict__ Wq, const float* __restrict__ Wk,
    const float* __restrict__ Wv, const float* __restrict__ Wo,
    const float* __restrict__ ff1w, const float* __restrict__ ff2w)
{
    int gid = blockIdx.x * 256 + threadIdx.x;
    int lane, lg, lc;
    if (gid < 16384) {                                    // Wq
        int e = gid;
        lane = e & 31; lg = lane >> 2; lc = lane & 3;
        int t = e >> 5, ntile = t & 31, ks = t >> 5;
        int k0 = ks * 16 + 2 * lc, n = ntile * 8 + lg;
        uint2 p0 = bsplit2(Wq[k0 * 256 + n], Wq[(k0 + 1) * 256 + n]);
        uint2 p1 = bsplit2(Wq[(k0 + 8) * 256 + n], Wq[(k0 + 9) * 256 + n]);
        g_wqf[e] = make_uint4(p0.x, p0.y, p1.x, p1.y);
    } else if (gid < 32768) {                             // Wo
        int e = gid - 16384;
        lane = e & 31; lg = lane >> 2; lc = lane & 3;
        int t = e >> 5, ntile = t & 31, ks = t >> 5;
        int k0 = ks * 16 + 2 * lc, n = ntile * 8 + lg;
        uint2 p0 = bsplit2(Wo[k0 * 256 + n], Wo[(k0 + 1) * 256 + n]);
        uint2 p1 = bsplit2(Wo[(k0 + 8) * 256 + n], Wo[(k0 + 9) * 256 + n]);
        g_wof[e] = make_uint4(p0.x, p0.y, p1.x, p1.y);
    } else if (gid < 49152) {                             // Wk per head
        int e = gid - 32768;
        lane = e & 31; lg = lane >> 2; lc = lane & 3;
        int t = e >> 5, ntile = t & 31, hk = t >> 5;
        int h = hk >> 1, ks2 = hk & 1;
        int k0 = ks2 * 16 + 2 * lc, n = ntile * 8 + lg;
        const float* base = Wk + n * 256 + h * 32;
        uint2 p0 = bsplit2(base[k0], base[k0 + 1]);
        uint2 p1 = bsplit2(base[k0 + 8], base[k0 + 9]);
        g_wkf[e] = make_uint4(p0.x, p0.y, p1.x, p1.y);
    } else if (gid < 65536) {                             // Wv per head
        int e = gid - 49152;
        lane = e & 31; lg = lane >> 2; lc = lane & 3;
        int t = e >> 5, nt = t & 3, u2 = t >> 2;
        int ks = u2 & 15, hd = u2 >> 4;
        int k0 = ks * 16 + 2 * lc, n = hd * 32 + nt * 8 + lg;
        uint2 p0 = bsplit2(Wv[k0 * 256 + n], Wv[(k0 + 1) * 256 + n]);
        uint2 p1 = bsplit2(Wv[(k0 + 8) * 256 + n], Wv[(k0 + 9) * 256 + n]);
        g_wvf[e] = make_uint4(p0.x, p0.y, p1.x, p1.y);
    } else if (gid < 131072) {                            // ff1w
        int e = gid - 65536;
        lane = e & 31; lg = lane >> 2; lc = lane & 3;
        int t = e >> 5, ntile = t & 127, ks = t >> 7;
        int k0 = ks * 16 + 2 * lc, n = ntile * 8 + lg;
        uint2 p0 = bsplit2(ff1w[k0 * FFn + n], ff1w[(k0 + 1) * FFn + n]);
        uint2 p1 = bsplit2(ff1w[(k0 + 8) * FFn + n], ff1w[(k0 + 9) * FFn + n]);
        g_w1f[e] = make_uint4(p0.x, p0.y, p1.x, p1.y);
    } else if (gid < 196608) {                            // ff2w
        int e = gid - 131072;
        lane = e & 31; lg = lane >> 2; lc = lane & 3;
        int t = e >> 5, ntile = t & 31, ks = t >> 5;
        int k0 = ks * 16 + 2 * lc, n = ntile * 8 + lg;
        uint2 p0 = bsplit2(ff2w[k0 * 256 + n], ff2w[(k0 + 1) * 256 + n]);
        uint2 p1 = bsplit2(ff2w[(k0 + 8) * 256 + n], ff2w[(k0 + 9) * 256 + n]);
        g_w2f[e] = make_uint4(p0.x, p0.y, p1.x, p1.y);
    }
}

// ---------------------------------------------------------------------------
// Attention: 8 anchors / CTA, 512 threads, 2 CTAs/SM.  All GEMM phases +
// scores on bf16 mma; u scalar with paired columns.
// ---------------------------------------------------------------------------
__global__ __launch_bounds__(512, 2) void attn11(
    const float* __restrict__ x_anc, const float* __restrict__ x_nei,
    const float* __restrict__ g1, const float* __restrict__ b1)
{
    extern __shared__ float sf[];
    float* hS  = sf + SM_H;
    float* qS  = sf + SM_QS;                  // later oS
    uint4* cB  = (uint4*)(sf + SM_CB);        // [8a][16ks][32lane]
    uint2* uB  = (uint2*)(sf + SM_CB);        // later: [64 rows][130 pairs]
    float* sS  = sf + SM_SS;
    float* aS4 = sf + SM_A4;
    float* oS  = qS;

    const int tid = threadIdx.x, wid = tid >> 5, lane = tid & 31;
    const int lg = lane >> 2, lc = lane & 3;
    const int b0 = blockIdx.x * 8;

    // ---- LN1 ----
    if (wid < 8) {
        const float* xr = x_anc + (size_t)(b0 + wid) * Dn;
        float4 v0 = *(const float4*)&xr[lane * 8];
        float4 v1 = *(const float4*)&xr[lane * 8 + 4];
        float v[8] = {v0.x, v0.y, v0.z, v0.w, v1.x, v1.y, v1.z, v1.w};
        float s = 0.f, s2 = 0.f;
        #pragma unroll
        for (int t = 0; t < 8; t++) { s += v[t]; s2 += v[t] * v[t]; }
        #pragma unroll
        for (int o = 16; o; o >>= 1) {
            s  += __shfl_xor_sync(0xffffffffu, s,  o);
            s2 += __shfl_xor_sync(0xffffffffu, s2, o);
        }
        const float mu   = s * (1.0f / Dn);
        const float var  = s2 * (1.0f / Dn) - mu * mu;
        const float rstd = rsqrtf(var + 1e-5f);
        #pragma unroll
        for (int t = 0; t < 8; t++) {
            const int c = lane * 8 + t;
            hS[wid * 268 + c] = (v[t] - mu) * rstd * g1[c] + b1[c];
        }
    }
    __syncthreads();

    // ---- Q = h @ Wq (bf16 mma, M=8) ----
    {
        float acc[2][4] = {{0.f,0.f,0.f,0.f},{0.f,0.f,0.f,0.f}};
        #pragma unroll
        for (int ks = 0; ks < 16; ks++) {
            const int kb = ks * 16;
            float2 p0 = *(const float2*)&hS[lg * 268 + kb + 2 * lc];
            float2 p1 = *(const float2*)&hS[lg * 268 + kb + 8 + 2 * lc];
            uint32_t Ah[4], Al[4];
            asplit(p0.x, p0.y, Ah[0], Al[0]);
            asplit(p1.x, p1.y, Ah[2], Al[2]);
            Ah[1] = Al[1] = Ah[3] = Al[3] = 0u;
            #pragma unroll
            for (int nt = 0; nt < 2; nt++) {
                uint4 v = g_wqf[(ks * 32 + wid * 2 + nt) * 32 + lane];
                uint32_t bh[2] = {v.x, v.z}, bl[2] = {v.y, v.w};
                mmabf(acc[nt], Ah, bh);
                mmabf(acc[nt], Ah, bl);
                mmabf(acc[nt], Al, bh);
            }
        }
        __syncthreads();
        #pragma unroll
        for (int nt = 0; nt < 2; nt++) {
            const int col = wid * 16 + nt * 8 + lc * 2;
            qS[lg * 268 + col]     = acc[nt][0];
            qS[lg * 268 + col + 1] = acc[nt][1];
        }
    }
    __syncthreads();

    // ---- c[a][h][:] (bf16 mma per head) -> cB frag table (split pairs) ----
    {
        #pragma unroll
        for (int h = 0; h < 8; h++) {
            float acc[2][4] = {{0.f,0.f,0.f,0.f},{0.f,0.f,0.f,0.f}};
            #pragma unroll
            for (int ks2 = 0; ks2 < 2; ks2++) {
                const int kb = h * 32 + ks2 * 16;
                float2 p0 = *(const float2*)&qS[lg * 268 + kb + 2 * lc];
                float2 p1 = *(const float2*)&qS[lg * 268 + kb + 8 + 2 * lc];
                uint32_t Ah[4], Al[4];
                asplit(p0.x, p0.y, Ah[0], Al[0]);
                asplit(p1.x, p1.y, Ah[2], Al[2]);
                Ah[1] = Al[1] = Ah[3] = Al[3] = 0u;
                #pragma unroll
                for (int nt = 0; nt < 2; nt++) {
                    uint4 v = g_wkf[((h * 2 + ks2) * 32 + wid * 2 + nt) * 32 + lane];
                    uint32_t bh[2] = {v.x, v.z}, bl[2] = {v.y, v.w};
                    mmabf(acc[nt], Ah, bh);
                    mmabf(acc[nt], Ah, bl);
                    mmabf(acc[nt], Al, bh);
                }
            }
            // store into cB: element (a=lg, head=h, d = wid*16 + nt*8 + 2lc,+1)
            // cB[a][ks=wid][lane' = h*4+lc], uint4 half nt
            #pragma unroll
            for (int nt = 0; nt < 2; nt++) {
                uint2 pr = bsplit2(acc[nt][0], acc[nt][1]);
                uint2* dst = (uint2*)&cB[(lg * 16 + wid) * 32 + h * 4 + lc];
                dst[nt] = pr;
            }
        }
    }
    __syncthreads();

    // ---- scores via bf16 mma: warp = (anchor a = wid>>1, M-tile mt = wid&1) ----
    {
        const int a = wid >> 1, mt = wid & 1;
        const float* xb = x_nei + (size_t)(b0 + a) * (KN * Dn);
        const int r0 = mt * 16 + lg, r1 = r0 + 8;
        float acc[4] = {0.f, 0.f, 0.f, 0.f};
        #pragma unroll 4
        for (int ks = 0; ks < 16; ks++) {
            const int kb = ks * 16 + 2 * lc;
            float2 x0 = *(const float2*)&xb[r0 * Dn + kb];
            float2 x1 = *(const float2*)&xb[r1 * Dn + kb];
            float2 x2 = *(const float2*)&xb[r0 * Dn + kb + 8];
            float2 x3 = *(const float2*)&xb[r1 * Dn + kb + 8];
            uint32_t Ah[4], Al[4];
            asplit(x0.x, x0.y, Ah[0], Al[0]);
            asplit(x1.x, x1.y, Ah[1], Al[1]);
            asplit(x2.x, x2.y, Ah[2], Al[2]);
            asplit(x3.x, x3.y, Ah[3], Al[3]);
            uint4 v = cB[(a * 16 + ks) * 32 + lane];
            uint32_t bh[2] = {v.x, v.z}, bl[2] = {v.y, v.w};
            mmabf(acc, Ah, bh);
            mmabf(acc, Ah, bl);
            mmabf(acc, Al, bh);
        }
        // C: (neighbor mt*16+lg / +8, head 2lc / 2lc+1)
        sS[(a * 8 + 2 * lc)     * 33 + r0] = acc[0];
        sS[(a * 8 + 2 * lc + 1) * 33 + r0] = acc[1];
        sS[(a * 8 + 2 * lc)     * 33 + r1] = acc[2];
        sS[(a * 8 + 2 * lc + 1) * 33 + r1] = acc[3];
    }
    __syncthreads();

    // ---- softmax -> aS4[a][k][h] ----
    {
        #pragma unroll
        for (int rr = 0; rr < 4; rr++) {
            const int r = wid * 4 + rr;
            const int a = r >> 3, h = r & 7;
            float sc = sS[r * 33 + lane] * 0.17677669529663687f;
            float m = sc;
            #pragma unroll
            for (int o = 16; o; o >>= 1)
                m = fmaxf(m, __shfl_xor_sync(0xffffffffu, m, o));
            float e = expf(sc - m), es = e;
            #pragma unroll
            for (int o = 16; o; o >>= 1)
                es += __shfl_xor_sync(0xffffffffu, es, o);
            aS4[a * 264 + lane * 8 + h] = e / es;
        }
    }
    __syncthreads();

    // ---- u: thread = (col-pair pc, group) -> 2 anchors; write split pairs uB ----
    {
        const int pc = tid & 127;
        const int a0g = (tid >> 7) * 2;
        #pragma unroll
        for (int a = 0; a < 2; a++) {
            const int ag = a0g + a;
            const float* xb = x_nei + (size_t)(b0 + ag) * (KN * Dn) + 2 * pc;
            float u0[8] = {0,0,0,0,0,0,0,0}, u1[8] = {0,0,0,0,0,0,0,0};
            #pragma unroll
            for (int k = 0; k < 32; k++) {
                float2 xv = *(const float2*)&xb[k * Dn];
                float4 af0 = *(const float4*)&aS4[ag * 264 + k * 8];
                float4 af1 = *(const float4*)&aS4[ag * 264 + k * 8 + 4];
                u0[0] = fmaf(af0.x, xv.x, u0[0]); u1[0] = fmaf(af0.x, xv.y, u1[0]);
                u0[1] = fmaf(af0.y, xv.x, u0[1]); u1[1] = fmaf(af0.y, xv.y, u1[1]);
                u0[2] = fmaf(af0.z, xv.x, u0[2]); u1[2] = fmaf(af0.z, xv.y, u1[2]);
                u0[3] = fmaf(af0.w, xv.x, u0[3]); u1[3] = fmaf(af0.w, xv.y, u1[3]);
                u0[4] = fmaf(af1.x, xv.x, u0[4]); u1[4] = fmaf(af1.x, xv.y, u1[4]);
                u0[5] = fmaf(af1.y, xv.x, u0[5]); u1[5] = fmaf(af1.y, xv.y, u1[5]);
                u0[6] = fmaf(af1.z, xv.x, u0[6]); u1[6] = fmaf(af1.z, xv.y, u1[6]);
                u0[7] = fmaf(af1.w, xv.x, u0[7]); u1[7] = fmaf(af1.w, xv.y, u1[7]);
            }
            #pragma unroll
            for (int h = 0; h < 8; h++)
                uB[(h * 8 + ag) * 130 + pc] = bsplit2(u0[h], u1[h]);
        }
    }
    __syncthreads();

    // ---- Wv (bf16 mma per head; warp-pair shares head; A pre-split in uB) ----
    {
        const int hd = wid >> 1;
        const int ntb = (wid & 1) * 2;
        float acc[2][4] = {{0.f,0.f,0.f,0.f},{0.f,0.f,0.f,0.f}};
        #pragma unroll
        for (int ks = 0; ks < 16; ks++) {
            uint2 q0 = uB[(hd * 8 + lg) * 130 + ks * 8 + lc];
            uint2 q1 = uB[(hd * 8 + lg) * 130 + ks * 8 + 4 + lc];
            uint32_t Ah[4], Al[4];
            Ah[0] = q0.x; Al[0] = q0.y;
            Ah[2] = q1.x; Al[2] = q1.y;
            Ah[1] = Al[1] = Ah[3] = Al[3] = 0u;
            #pragma unroll
            for (int uu = 0; uu < 2; uu++) {
                const int nt = ntb + uu;
                uint4 v = g_wvf[((hd * 16 + ks) * 4 + nt) * 32 + lane];
                uint32_t bh[2] = {v.x, v.z}, bl[2] = {v.y, v.w};
                mmabf(acc[uu], Ah, bh);
                mmabf(acc[uu], Ah, bl);
                mmabf(acc[uu], Al, bh);
            }
        }
        __syncthreads();
        #pragma unroll
        for (int uu = 0; uu < 2; uu++) {
            const int col = hd * 32 + (ntb + uu) * 8 + lc * 2;
            oS[lg * 268 + col]     = acc[uu][0];
            oS[lg * 268 + col + 1] = acc[uu][1];
        }
    }
    __syncthreads();

    // ---- x = x_anc + oS @ Wo (bf16 mma) ----
    {
        float acc[2][4] = {{0.f,0.f,0.f,0.f},{0.f,0.f,0.f,0.f}};
        #pragma unroll
        for (int ks = 0; ks < 16; ks++) {
            const int kb = ks * 16;
            float2 p0 = *(const float2*)&oS[lg * 268 + kb + 2 * lc];
            float2 p1 = *(const float2*)&oS[lg * 268 + kb + 8 + 2 * lc];
            uint32_t Ah[4], Al[4];
            asplit(p0.x, p0.y, Ah[0], Al[0]);
            asplit(p1.x, p1.y, Ah[2], Al[2]);
            Ah[1] = Al[1] = Ah[3] = Al[3] = 0u;
            #pragma unroll
            for (int nt = 0; nt < 2; nt++) {
                uint4 v = g_wof[(ks * 32 + wid * 2 + nt) * 32 + lane];
                uint32_t bh[2] = {v.x, v.z}, bl[2] = {v.y, v.w};
                mmabf(acc[nt], Ah, bh);
                mmabf(acc[nt], Ah, bl);
                mmabf(acc[nt], Al, bh);
            }
        }
        #pragma unroll
        for (int nt = 0; nt < 2; nt++) {
            const int col = wid * 16 + nt * 8 + lc * 2;
            const size_t idx = (size_t)(b0 + lg) * Dn + col;
            g_x[idx]     = x_anc[idx]     + acc[nt][0];
            g_x[idx + 1] = x_anc[idx + 1] + acc[nt][1];
        }
    }
}

// ---------------------------------------------------------------------------
// FFN (unchanged R11 bf16 version)
// ---------------------------------------------------------------------------
__global__ __launch_bounds__(512, 1) void ffn_bf(
    const float* __restrict__ ln2g, const float* __restrict__ ln2b,
    const float* __restrict__ ff1b, const float* __restrict__ ff2b,
    float* __restrict__ out)
{
    extern __shared__ uint2 su[];
    uint2* hHL = su;
    uint2* act = su + 32 * FH2;

    const int tid = threadIdx.x, wid = tid >> 5, lane = tid & 31;
    const int lg = lane >> 2, lc = lane & 3;
    const int row0 = blockIdx.x * 32;

    #pragma unroll
    for (int rr = 0; rr < 2; rr++) {
        const int row = wid * 2 + rr;
        const float* xr = g_x + (size_t)(row0 + row) * Dn;
        float4 v0 = *(const float4*)&xr[lane * 8];
        float4 v1 = *(const float4*)&xr[lane * 8 + 4];
        float v[8] = {v0.x, v0.y, v0.z, v0.w, v1.x, v1.y, v1.z, v1.w};
        float s = 0.f, s2 = 0.f;
        #pragma unroll
        for (int t = 0; t < 8; t++) { s += v[t]; s2 += v[t] * v[t]; }
        #pragma unroll
        for (int o = 16; o; o >>= 1) {
            s  += __shfl_xor_sync(0xffffffffu, s,  o);
            s2 += __shfl_xor_sync(0xffffffffu, s2, o);
        }
        const float mu   = s * (1.0f / Dn);
        const float var  = s2 * (1.0f / Dn) - mu * mu;
        const float rstd = rsqrtf(var + 1e-5f);
        float hv[8];
        #pragma unroll
        for (int t = 0; t < 8; t++) {
            const int c = lane * 8 + t;
            hv[t] = (v[t] - mu) * rstd * ln2g[c] + ln2b[c];
        }
        #pragma unroll
        for (int t = 0; t < 4; t++)
            hHL[row * FH2 + lane * 4 + t] = bsplit2(hv[2 * t], hv[2 * t + 1]);
    }
    __syncthreads();

    float acc2[2][2][4];
    #pragma unroll
    for (int mt = 0; mt < 2; mt++)
        #pragma unroll
        for (int nt = 0; nt < 2; nt++)
            #pragma unroll
            for (int e = 0; e < 4; e++) acc2[mt][nt][e] = 0.f;

    for (int half = 0; half < 2; half++) {
        float acc[2][4][4];
        #pragma unroll
        for (int mt = 0; mt < 2; mt++)
            #pragma unroll
            for (int nt = 0; nt < 4; nt++)
                #pragma unroll
                for (int e = 0; e < 4; e++) acc[mt][nt][e] = 0.f;

        #pragma unroll 4
        for (int ks = 0; ks < 16; ks++) {
            const int kb2 = ks * 8;
            uint32_t Ah[2][4], Al[2][4];
            #pragma unroll
            for (int mt = 0; mt < 2; mt++) {
                const int r0 = mt * 16 + lg;
                uint2 q0 = hHL[r0 * FH2 + kb2 + lc];
                uint2 q1 = hHL[(r0 + 8) * FH2 + kb2 + lc];
                uint2 q2 = hHL[r0 * FH2 + kb2 + 4 + lc];
                uint2 q3 = hHL[(r0 + 8) * FH2 + kb2 + 4 + lc];
                Ah[mt][0] = q0.x; Al[mt][0] = q0.y;
                Ah[mt][1] = q1.x; Al[mt][1] = q1.y;
                Ah[mt][2] = q2.x; Al[mt][2] = q2.y;
                Ah[mt][3] = q3.x; Al[mt][3] = q3.y;
            }
            #pragma unroll
            for (int nt = 0; nt < 4; nt++) {
                const int ntile = half * 64 + wid * 4 + nt;
                uint4 v = g_w1f[(ks * 128 + ntile) * 32 + lane];
                uint32_t bh[2] = {v.x, v.z}, bl[2] = {v.y, v.w};
                #pragma unroll
                for (int mt = 0; mt < 2; mt++) {
                    mmabf(acc[mt][nt], Ah[mt], bh);
                    mmabf(acc[mt][nt], Ah[mt], bl);
                    mmabf(acc[mt][nt], Al[mt], bh);
                }
            }
        }

        #pragma unroll
        for (int mt = 0; mt < 2; mt++) {
            const int r0 = mt * 16 + lg;
            #pragma unroll
            for (int nt = 0; nt < 4; nt++) {
                const int lcol = wid * 32 + nt * 8 + lc * 2;
                const int gcol = half * 512 + lcol;
                const float b0 = ff1b[gcol], b1 = ff1b[gcol + 1];
                float u0 = acc[mt][nt][0] + b0;
                float u1 = acc[mt][nt][1] + b1;
                float u2 = acc[mt][nt][2] + b0;
                float u3 = acc[mt][nt][3] + b1;
                float g0 = 0.5f * u0 * (1.0f + erff(u0 * 0.70710678118654752f));
                float g1v = 0.5f * u1 * (1.0f + erff(u1 * 0.70710678118654752f));
                float g2 = 0.5f * u2 * (1.0f + erff(u2 * 0.70710678118654752f));
                float g3 = 0.5f * u3 * (1.0f + erff(u3 * 0.70710678118654752f));
                const int pidx = lcol >> 1;
                act[r0 * FA2 + pidx]       = bsplit2(g0, g1v);
                act[(r0 + 8) * FA2 + pidx] = bsplit2(g2, g3);
            }
        }
        __syncthreads();

        #pragma unroll 4
        for (int ks = 0; ks < 32; ks++) {
            const int kb2 = ks * 8;
            uint32_t Ah[2][4], Al[2][4];
            #pragma unroll
            for (int mt = 0; mt < 2; mt++) {
                const int r0 = mt * 16 + lg;
                uint2 q0 = act[r0 * FA2 + kb2 + lc];
                uint2 q1 = act[(r0 + 8) * FA2 + kb2 + lc];
                uint2 q2 = act[r0 * FA2 + kb2 + 4 + lc];
                uint2 q3 = act[(r0 + 8) * FA2 + kb2 + 4 + lc];
                Ah[mt][0] = q0.x; Al[mt][0] = q0.y;
                Ah[mt][1] = q1.x; Al[mt][1] = q1.y;
                Ah[mt][2] = q2.x; Al[mt][2] = q2.y;
                Ah[mt][3] = q3.x; Al[mt][3] = q3.y;
            }
            const int ksg = half * 32 + ks;
            #pragma unroll
            for (int nt = 0; nt < 2; nt++) {
                const int ntile = wid * 2 + nt;
                uint4 v = g_w2f[(ksg * 32 + ntile) * 32 + lane];
                uint32_t bh[2] = {v.x, v.z}, bl[2] = {v.y, v.w};
                #pragma unroll
                for (int mt = 0; mt < 2; mt++) {
                    mmabf(acc2[mt][nt], Ah[mt], bh);
                    mmabf(acc2[mt][nt], Ah[mt], bl);
                    mmabf(acc2[mt][nt], Al[mt], bh);
                }
            }
        }
        __syncthreads();
    }

    #pragma unroll
    for (int mt = 0; mt < 2; mt++) {
        const int r0 = mt * 16 + lg;
        #pragma unroll
        for (int nt = 0; nt < 2; nt++) {
            const int col = wid * 16 + nt * 8 + lc * 2;
            const float b0 = ff2b[col], b1 = ff2b[col + 1];
            const size_t i0 = (size_t)(row0 + r0) * Dn + col;
            const size_t i1 = (size_t)(row0 + r0 + 8) * Dn + col;
            out[i0]     = g_x[i0]     + acc2[mt][nt][0] + b0;
            out[i0 + 1] = g_x[i0 + 1] + acc2[mt][nt][1] + b1;
            out[i1]     = g_x[i1]     + acc2[mt][nt][2] + b0;
            out[i1 + 1] = g_x[i1 + 1] + acc2[mt][nt][3] + b1;
        }
    }
}

extern "C" void kernel_launch(void* const* d_in, const int* in_sizes, int n_in,
                              void* d_out, int out_size)
{
    const float* x_anc = (const float*)d_in[0];
    const float* x_nei = (const float*)d_in[1];
    const float* Wq    = (const float*)d_in[2];
    const float* Wk    = (const float*)d_in[3];
    const float* Wv    = (const float*)d_in[4];
    const float* Wo    = (const float*)d_in[5];
    const float* ln1g  = (const float*)d_in[6];
    const float* ln1b  = (const float*)d_in[7];
    const float* ln2g  = (const float*)d_in[8];
    const float* ln2b  = (const float*)d_in[9];
    const float* ff1w  = (const float*)d_in[10];
    const float* ff1b  = (const float*)d_in[11];
    const float* ff2w  = (const float*)d_in[12];
    const float* ff2b  = (const float*)d_in[13];
    float* out = (float*)d_out;

    static bool attr_set = false;
    if (!attr_set) {
        cudaFuncSetAttribute(attn11, cudaFuncAttributeMaxDynamicSharedMemorySize, ATTN_SMEM);
        cudaFuncSetAttribute(ffn_bf, cudaFuncAttributeMaxDynamicSharedMemorySize, FFN_SMEM);
        attr_set = true;
    }

    split_all<<<768, 256>>>(Wq, Wk, Wv, Wo, ff1w, ff2w);
    attn11<<<Bn / 8, 512, ATTN_SMEM>>>(x_anc, x_nei, ln1g, ln1b);
    ffn_bf<<<Bn / 32, 512, FFN_SMEM>>>(ln2g, ln2b, ff1b, ff2b, out);
}